// round 5
// baseline (speedup 1.0000x reference)
#include <cuda_runtime.h>

// ---------------------------------------------------------------------------
// PAM module: dual attention (over W and over H) on template (64x64) and
// scene (128x128) maps. B=16, C=256, C8=32.
//
// All heavy ops are fp32 smem-tiled GEMMs (64x64 block tile, 16-deep K tile,
// 4x4 per-thread micro tile, 256 threads).
// ---------------------------------------------------------------------------

#define B_    16
#define C_    256
#define C8_   32
#define MROWS 320   // 32 (q) + 32 (k) + 256 (v)

// Scratch (device globals: allocation-free rule)
__device__ float g_qkv[(size_t)B_ * MROWS * 128 * 128];   // 335 MB, scene-sized
__device__ float g_att[(size_t)B_ * 128 * 128];           // logits / attention (in place)
__device__ float g_wc[MROWS * C_];
__device__ float g_bc[MROWS];

// ---------------------------------------------------------------------------
// Build stacked weight [320,256] and bias [320] for one branch.
// ---------------------------------------------------------------------------
__global__ void build_wc_kernel(const float* __restrict__ qw, const float* __restrict__ qb,
                                const float* __restrict__ kw, const float* __restrict__ kb,
                                const float* __restrict__ vw, const float* __restrict__ vb,
                                int br) {
    int i = blockIdx.x * blockDim.x + threadIdx.x;
    if (i < MROWS * C_) {
        int m = i / C_, k = i % C_;
        float val;
        if (m < 32)       val = qw[(size_t)br * 32 * C_ + m * C_ + k];
        else if (m < 64)  val = kw[(size_t)br * 32 * C_ + (m - 32) * C_ + k];
        else              val = vw[(size_t)br * C_ * C_ + (m - 64) * C_ + k];
        g_wc[i] = val;
    }
    if (i < MROWS) {
        g_bc[i] = (i < 32) ? qb[br * 32 + i]
                : (i < 64) ? kb[br * 32 + i - 32]
                           : vb[br * C_ + i - 64];
    }
}

// ---------------------------------------------------------------------------
// QKV projection: Out[b, m, n] = sum_k Wc[m,k] * X[b,k,n] + bc[m]
// M = 320, N = S*S, K = 256.  grid = (N/64, 5, B)
// ---------------------------------------------------------------------------
__global__ __launch_bounds__(256)
void proj_kernel(const float* __restrict__ x, int HW) {
    __shared__ float As[16][68];
    __shared__ float Bs[16][68];
    int b  = blockIdx.z;
    int m0 = blockIdx.y * 64;
    int n0 = blockIdx.x * 64;
    const float* Xb = x + (size_t)b * C_ * HW;
    float*       Ob = g_qkv + (size_t)b * MROWS * HW;

    int tid = threadIdx.x;
    int tx = tid & 15, ty = tid >> 4;
    float acc[4][4] = {};

    for (int k0 = 0; k0 < C_; k0 += 16) {
#pragma unroll
        for (int i = 0; i < 4; ++i) {           // Wc[m0+m][k0+k] -> As[k][m]
            int idx = tid + i * 256;
            int m = idx >> 4, k = idx & 15;
            As[k][m] = g_wc[(m0 + m) * C_ + k0 + k];
        }
#pragma unroll
        for (int i = 0; i < 4; ++i) {           // X[k0+k][n0+n] -> Bs[k][n] (coalesced)
            int idx = tid + i * 256;
            int n = idx & 63, k = idx >> 6;
            Bs[k][n] = Xb[(size_t)(k0 + k) * HW + n0 + n];
        }
        __syncthreads();
#pragma unroll
        for (int k = 0; k < 16; ++k) {
            float a[4], bb[4];
#pragma unroll
            for (int i = 0; i < 4; ++i) a[i]  = As[k][ty * 4 + i];
#pragma unroll
            for (int j = 0; j < 4; ++j) bb[j] = Bs[k][tx * 4 + j];
#pragma unroll
            for (int i = 0; i < 4; ++i)
#pragma unroll
                for (int j = 0; j < 4; ++j) acc[i][j] += a[i] * bb[j];
        }
        __syncthreads();
    }
#pragma unroll
    for (int i = 0; i < 4; ++i) {
        int m = m0 + ty * 4 + i;
        float bias = g_bc[m];
#pragma unroll
        for (int j = 0; j < 4; ++j)
            Ob[(size_t)m * HW + n0 + tx * 4 + j] = acc[i][j] + bias;
    }
}

// ---------------------------------------------------------------------------
// Logits over W: E[b,w,v] = sum_{o,h} Q[b,o,h,w] * K[b,o,h,v]
// Q flat = [F=C8*S, S] row-major.  M=N=S, K=F.  grid = (S/64, S/64, B)
// ---------------------------------------------------------------------------
__global__ __launch_bounds__(256)
void logits_w_kernel(int S) {
    __shared__ float As[16][68];
    __shared__ float Bs[16][68];
    int SS = S * S;
    int F  = C8_ * S;
    const float* Qb = g_qkv + (size_t)blockIdx.z * MROWS * SS;
    const float* Kb = Qb + (size_t)32 * SS;
    float*       Eb = g_att + (size_t)blockIdx.z * SS;

    int m0 = blockIdx.y * 64, n0 = blockIdx.x * 64;
    int tid = threadIdx.x;
    int tx = tid & 15, ty = tid >> 4;
    float acc[4][4] = {};

    for (int k0 = 0; k0 < F; k0 += 16) {
#pragma unroll
        for (int i = 0; i < 4; ++i) {
            int idx = tid + i * 256;
            int n = idx & 63, k = idx >> 6;
            As[k][n] = Qb[(size_t)(k0 + k) * S + m0 + n];
            Bs[k][n] = Kb[(size_t)(k0 + k) * S + n0 + n];
        }
        __syncthreads();
#pragma unroll
        for (int k = 0; k < 16; ++k) {
            float a[4], bb[4];
#pragma unroll
            for (int i = 0; i < 4; ++i) a[i]  = As[k][ty * 4 + i];
#pragma unroll
            for (int j = 0; j < 4; ++j) bb[j] = Bs[k][tx * 4 + j];
#pragma unroll
            for (int i = 0; i < 4; ++i)
#pragma unroll
                for (int j = 0; j < 4; ++j) acc[i][j] += a[i] * bb[j];
        }
        __syncthreads();
    }
#pragma unroll
    for (int i = 0; i < 4; ++i)
#pragma unroll
        for (int j = 0; j < 4; ++j)
            Eb[(size_t)(m0 + ty * 4 + i) * S + n0 + tx * 4 + j] = acc[i][j];
}

// ---------------------------------------------------------------------------
// Logits over H: E[b,h,v] = sum_{o,w} Q[b,o,h,w] * K[b,o,v,w]
// K-dim f = o*S + w (tiles never cross o since 16 | S). grid = (S/64, S/64, B)
// ---------------------------------------------------------------------------
__global__ __launch_bounds__(256)
void logits_h_kernel(int S) {
    __shared__ float As[16][68];
    __shared__ float Bs[16][68];
    int SS = S * S;
    int F  = C8_ * S;
    const float* Qb = g_qkv + (size_t)blockIdx.z * MROWS * SS;
    const float* Kb = Qb + (size_t)32 * SS;
    float*       Eb = g_att + (size_t)blockIdx.z * SS;

    int m0 = blockIdx.y * 64, n0 = blockIdx.x * 64;
    int tid = threadIdx.x;
    int tx = tid & 15, ty = tid >> 4;
    float acc[4][4] = {};

    for (int k0 = 0; k0 < F; k0 += 16) {
        int o  = k0 / S;
        int w0 = k0 % S;
        const float* Qo = Qb + (size_t)o * SS;
        const float* Ko = Kb + (size_t)o * SS;
#pragma unroll
        for (int i = 0; i < 4; ++i) {
            int idx = tid + i * 256;
            int k = idx & 15, m = idx >> 4;
            As[k][m] = Qo[(size_t)(m0 + m) * S + w0 + k];
            Bs[k][m] = Ko[(size_t)(n0 + m) * S + w0 + k];
        }
        __syncthreads();
#pragma unroll
        for (int k = 0; k < 16; ++k) {
            float a[4], bb[4];
#pragma unroll
            for (int i = 0; i < 4; ++i) a[i]  = As[k][ty * 4 + i];
#pragma unroll
            for (int j = 0; j < 4; ++j) bb[j] = Bs[k][tx * 4 + j];
#pragma unroll
            for (int i = 0; i < 4; ++i)
#pragma unroll
                for (int j = 0; j < 4; ++j) acc[i][j] += a[i] * bb[j];
        }
        __syncthreads();
    }
#pragma unroll
    for (int i = 0; i < 4; ++i)
#pragma unroll
        for (int j = 0; j < 4; ++j)
            Eb[(size_t)(m0 + ty * 4 + i) * S + n0 + tx * 4 + j] = acc[i][j];
}

// ---------------------------------------------------------------------------
// Row softmax in place on g_att: B*S rows of length S. blockDim = S.
// ---------------------------------------------------------------------------
__global__ void softmax_kernel(int S) {
    __shared__ float red[128];
    float* row = g_att + (size_t)blockIdx.x * S;
    int t = threadIdx.x;
    float v = row[t];
    red[t] = v;
    __syncthreads();
    for (int off = S >> 1; off > 0; off >>= 1) {
        if (t < off) red[t] = fmaxf(red[t], red[t + off]);
        __syncthreads();
    }
    float m = red[0];
    __syncthreads();
    float e = expf(v - m);
    red[t] = e;
    __syncthreads();
    for (int off = S >> 1; off > 0; off >>= 1) {
        if (t < off) red[t] += red[t + off];
        __syncthreads();
    }
    row[t] = e / red[0];
}

// ---------------------------------------------------------------------------
// Apply over W: out[b, m=(c*S+h), n=w] = 2*x + s * sum_v V[m,v]*A[w,v]
// V is rows [64,320) of QKV, contiguous [C*S, S]. grid = (S/64, C*S/64, B)
// ---------------------------------------------------------------------------
__global__ __launch_bounds__(256)
void apply_w_kernel(const float* __restrict__ x, float* __restrict__ out,
                    int S, const float* __restrict__ scalars, int br) {
    __shared__ float As[16][68];
    __shared__ float Bs[16][68];
    int SS = S * S;
    int b  = blockIdx.z;
    const float* Vb = g_qkv + (size_t)b * MROWS * SS + (size_t)64 * SS;
    const float* At = g_att + (size_t)b * SS;

    int m0 = blockIdx.y * 64, n0 = blockIdx.x * 64;
    int tid = threadIdx.x;
    int tx = tid & 15, ty = tid >> 4;
    float acc[4][4] = {};

    for (int k0 = 0; k0 < S; k0 += 16) {
#pragma unroll
        for (int i = 0; i < 4; ++i) {
            int idx = tid + i * 256;
            int k = idx & 15, m = idx >> 4;
            As[k][m] = Vb[(size_t)(m0 + m) * S + k0 + k];
            Bs[k][m] = At[(size_t)(n0 + m) * S + k0 + k];
        }
        __syncthreads();
#pragma unroll
        for (int k = 0; k < 16; ++k) {
            float a[4], bb[4];
#pragma unroll
            for (int i = 0; i < 4; ++i) a[i]  = As[k][ty * 4 + i];
#pragma unroll
            for (int j = 0; j < 4; ++j) bb[j] = Bs[k][tx * 4 + j];
#pragma unroll
            for (int i = 0; i < 4; ++i)
#pragma unroll
                for (int j = 0; j < 4; ++j) acc[i][j] += a[i] * bb[j];
        }
        __syncthreads();
    }
    float s = scalars[br];
#pragma unroll
    for (int i = 0; i < 4; ++i) {
        size_t base = (size_t)b * C_ * SS + (size_t)(m0 + ty * 4 + i) * S + n0 + tx * 4;
#pragma unroll
        for (int j = 0; j < 4; ++j)
            out[base + j] = 2.0f * x[base + j] + s * acc[i][j];
    }
}

// ---------------------------------------------------------------------------
// Apply over H: out[b,c,h,w] += s * sum_v A[h,v] * V[c,v,w]
// grid = (S/64, S/64, B*C)
// ---------------------------------------------------------------------------
__global__ __launch_bounds__(256)
void apply_h_kernel(float* __restrict__ out, int S,
                    const float* __restrict__ scalars, int br) {
    __shared__ float As[16][68];
    __shared__ float Bs[16][68];
    int SS = S * S;
    int bc = blockIdx.z;
    int b = bc / C_, c = bc % C_;
    const float* At = g_att + (size_t)b * SS;
    const float* Vc = g_qkv + (size_t)b * MROWS * SS + (size_t)(64 + c) * SS;

    int m0 = blockIdx.y * 64, n0 = blockIdx.x * 64;
    int tid = threadIdx.x;
    int tx = tid & 15, ty = tid >> 4;
    float acc[4][4] = {};

    for (int k0 = 0; k0 < S; k0 += 16) {
#pragma unroll
        for (int i = 0; i < 4; ++i) {
            int idx = tid + i * 256;
            {   // A[m][k] = At[(m0+m)*S + k0+k] -> As[k][m]
                int k = idx & 15, m = idx >> 4;
                As[k][m] = At[(size_t)(m0 + m) * S + k0 + k];
            }
            {   // B[k][n] = Vc[(k0+k)*S + n0+n] -> Bs[k][n] (coalesced)
                int n = idx & 63, k = idx >> 6;
                Bs[k][n] = Vc[(size_t)(k0 + k) * S + n0 + n];
            }
        }
        __syncthreads();
#pragma unroll
        for (int k = 0; k < 16; ++k) {
            float a[4], bb[4];
#pragma unroll
            for (int i = 0; i < 4; ++i) a[i]  = As[k][ty * 4 + i];
#pragma unroll
            for (int j = 0; j < 4; ++j) bb[j] = Bs[k][tx * 4 + j];
#pragma unroll
            for (int i = 0; i < 4; ++i)
#pragma unroll
                for (int j = 0; j < 4; ++j) acc[i][j] += a[i] * bb[j];
        }
        __syncthreads();
    }
    float s = scalars[br];
#pragma unroll
    for (int i = 0; i < 4; ++i) {
        size_t base = (size_t)b * C_ * SS + (size_t)c * SS
                    + (size_t)(m0 + ty * 4 + i) * S + n0 + tx * 4;
#pragma unroll
        for (int j = 0; j < 4; ++j)
            out[base + j] += s * acc[i][j];
    }
}

// ---------------------------------------------------------------------------
// Host-side orchestration
// ---------------------------------------------------------------------------
static void run_branch_pair(const float* x, int S, float* out,
                            int br_w, int br_h,
                            const float* qw, const float* qb,
                            const float* kw, const float* kb,
                            const float* vw, const float* vb,
                            const float* sc) {
    int SS = S * S;
    dim3 thr(256);

    // ---- over-W branch ----
    build_wc_kernel<<<(MROWS * C_ + 255) / 256, 256>>>(qw, qb, kw, kb, vw, vb, br_w);
    proj_kernel<<<dim3(SS / 64, MROWS / 64, B_), thr>>>(x, SS);
    logits_w_kernel<<<dim3(S / 64, S / 64, B_), thr>>>(S);
    softmax_kernel<<<B_ * S, S>>>(S);
    apply_w_kernel<<<dim3(S / 64, C_ * S / 64, B_), thr>>>(x, out, S, sc, br_w);

    // ---- over-H branch ----
    build_wc_kernel<<<(MROWS * C_ + 255) / 256, 256>>>(qw, qb, kw, kb, vw, vb, br_h);
    proj_kernel<<<dim3(SS / 64, MROWS / 64, B_), thr>>>(x, SS);
    logits_h_kernel<<<dim3(S / 64, S / 64, B_), thr>>>(S);
    softmax_kernel<<<B_ * S, S>>>(S);
    apply_h_kernel<<<dim3(S / 64, S / 64, B_ * C_), thr>>>(out, S, sc, br_h);
}

extern "C" void kernel_launch(void* const* d_in, const int* in_sizes, int n_in,
                              void* d_out, int out_size) {
    const float* tmap = (const float*)d_in[0];
    const float* smap = (const float*)d_in[1];
    const float* qw   = (const float*)d_in[2];
    const float* qb   = (const float*)d_in[3];
    const float* kw   = (const float*)d_in[4];
    const float* kb   = (const float*)d_in[5];
    const float* vw   = (const float*)d_in[6];
    const float* vb   = (const float*)d_in[7];
    const float* sc   = (const float*)d_in[8];

    float* tout = (float*)d_out;
    float* sout = tout + (size_t)B_ * C_ * 64 * 64;

    // template: branches 0 (over W), 2 (over H)
    run_branch_pair(tmap, 64, tout, 0, 2, qw, qb, kw, kb, vw, vb, sc);
    // scene: branches 1 (over W), 3 (over H)
    run_branch_pair(smap, 128, sout, 1, 3, qw, qb, kw, kb, vw, vb, sc);
}

// round 6
// speedup vs baseline: 1.0005x; 1.0005x over previous
#include <cuda_runtime.h>

// ---------------------------------------------------------------------------
// PAM module: dual attention (over W and over H) on template (64x64) and
// scene (128x128) maps. B=16, C=256, C8=32.
//
// All heavy ops are fp32 smem-tiled GEMMs (64x64 block tile, 16-deep K tile,
// 4x4 per-thread micro tile, 256 threads).
// ---------------------------------------------------------------------------

#define B_    16
#define C_    256
#define C8_   32
#define MROWS 320   // 32 (q) + 32 (k) + 256 (v)

// Scratch (device globals: allocation-free rule)
__device__ float g_qkv[(size_t)B_ * MROWS * 128 * 128];   // 335 MB, scene-sized
__device__ float g_att[(size_t)B_ * 128 * 128];           // logits / attention (in place)
__device__ float g_wc[MROWS * C_];
__device__ float g_bc[MROWS];

// ---------------------------------------------------------------------------
// Build stacked weight [320,256] and bias [320] for one branch.
// ---------------------------------------------------------------------------
__global__ void build_wc_kernel(const float* __restrict__ qw, const float* __restrict__ qb,
                                const float* __restrict__ kw, const float* __restrict__ kb,
                                const float* __restrict__ vw, const float* __restrict__ vb,
                                int br) {
    int i = blockIdx.x * blockDim.x + threadIdx.x;
    if (i < MROWS * C_) {
        int m = i / C_, k = i % C_;
        float val;
        if (m < 32)       val = qw[(size_t)br * 32 * C_ + m * C_ + k];
        else if (m < 64)  val = kw[(size_t)br * 32 * C_ + (m - 32) * C_ + k];
        else              val = vw[(size_t)br * C_ * C_ + (m - 64) * C_ + k];
        g_wc[i] = val;
    }
    if (i < MROWS) {
        g_bc[i] = (i < 32) ? qb[br * 32 + i]
                : (i < 64) ? kb[br * 32 + i - 32]
                           : vb[br * C_ + i - 64];
    }
}

// ---------------------------------------------------------------------------
// QKV projection: Out[b, m, n] = sum_k Wc[m,k] * X[b,k,n] + bc[m]
// M = 320, N = S*S, K = 256.  grid = (N/64, 5, B)
// ---------------------------------------------------------------------------
__global__ __launch_bounds__(256)
void proj_kernel(const float* __restrict__ x, int HW) {
    __shared__ float As[16][68];
    __shared__ float Bs[16][68];
    int b  = blockIdx.z;
    int m0 = blockIdx.y * 64;
    int n0 = blockIdx.x * 64;
    const float* Xb = x + (size_t)b * C_ * HW;
    float*       Ob = g_qkv + (size_t)b * MROWS * HW;

    int tid = threadIdx.x;
    int tx = tid & 15, ty = tid >> 4;
    float acc[4][4] = {};

    for (int k0 = 0; k0 < C_; k0 += 16) {
#pragma unroll
        for (int i = 0; i < 4; ++i) {           // Wc[m0+m][k0+k] -> As[k][m]
            int idx = tid + i * 256;
            int m = idx >> 4, k = idx & 15;
            As[k][m] = g_wc[(m0 + m) * C_ + k0 + k];
        }
#pragma unroll
        for (int i = 0; i < 4; ++i) {           // X[k0+k][n0+n] -> Bs[k][n] (coalesced)
            int idx = tid + i * 256;
            int n = idx & 63, k = idx >> 6;
            Bs[k][n] = Xb[(size_t)(k0 + k) * HW + n0 + n];
        }
        __syncthreads();
#pragma unroll
        for (int k = 0; k < 16; ++k) {
            float a[4], bb[4];
#pragma unroll
            for (int i = 0; i < 4; ++i) a[i]  = As[k][ty * 4 + i];
#pragma unroll
            for (int j = 0; j < 4; ++j) bb[j] = Bs[k][tx * 4 + j];
#pragma unroll
            for (int i = 0; i < 4; ++i)
#pragma unroll
                for (int j = 0; j < 4; ++j) acc[i][j] += a[i] * bb[j];
        }
        __syncthreads();
    }
#pragma unroll
    for (int i = 0; i < 4; ++i) {
        int m = m0 + ty * 4 + i;
        float bias = g_bc[m];
#pragma unroll
        for (int j = 0; j < 4; ++j)
            Ob[(size_t)m * HW + n0 + tx * 4 + j] = acc[i][j] + bias;
    }
}

// ---------------------------------------------------------------------------
// Logits over W: E[b,w,v] = sum_{o,h} Q[b,o,h,w] * K[b,o,h,v]
// Q flat = [F=C8*S, S] row-major.  M=N=S, K=F.  grid = (S/64, S/64, B)
// ---------------------------------------------------------------------------
__global__ __launch_bounds__(256)
void logits_w_kernel(int S) {
    __shared__ float As[16][68];
    __shared__ float Bs[16][68];
    int SS = S * S;
    int F  = C8_ * S;
    const float* Qb = g_qkv + (size_t)blockIdx.z * MROWS * SS;
    const float* Kb = Qb + (size_t)32 * SS;
    float*       Eb = g_att + (size_t)blockIdx.z * SS;

    int m0 = blockIdx.y * 64, n0 = blockIdx.x * 64;
    int tid = threadIdx.x;
    int tx = tid & 15, ty = tid >> 4;
    float acc[4][4] = {};

    for (int k0 = 0; k0 < F; k0 += 16) {
#pragma unroll
        for (int i = 0; i < 4; ++i) {
            int idx = tid + i * 256;
            int n = idx & 63, k = idx >> 6;
            As[k][n] = Qb[(size_t)(k0 + k) * S + m0 + n];
            Bs[k][n] = Kb[(size_t)(k0 + k) * S + n0 + n];
        }
        __syncthreads();
#pragma unroll
        for (int k = 0; k < 16; ++k) {
            float a[4], bb[4];
#pragma unroll
            for (int i = 0; i < 4; ++i) a[i]  = As[k][ty * 4 + i];
#pragma unroll
            for (int j = 0; j < 4; ++j) bb[j] = Bs[k][tx * 4 + j];
#pragma unroll
            for (int i = 0; i < 4; ++i)
#pragma unroll
                for (int j = 0; j < 4; ++j) acc[i][j] += a[i] * bb[j];
        }
        __syncthreads();
    }
#pragma unroll
    for (int i = 0; i < 4; ++i)
#pragma unroll
        for (int j = 0; j < 4; ++j)
            Eb[(size_t)(m0 + ty * 4 + i) * S + n0 + tx * 4 + j] = acc[i][j];
}

// ---------------------------------------------------------------------------
// Logits over H: E[b,h,v] = sum_{o,w} Q[b,o,h,w] * K[b,o,v,w]
// K-dim f = o*S + w (tiles never cross o since 16 | S). grid = (S/64, S/64, B)
// ---------------------------------------------------------------------------
__global__ __launch_bounds__(256)
void logits_h_kernel(int S) {
    __shared__ float As[16][68];
    __shared__ float Bs[16][68];
    int SS = S * S;
    int F  = C8_ * S;
    const float* Qb = g_qkv + (size_t)blockIdx.z * MROWS * SS;
    const float* Kb = Qb + (size_t)32 * SS;
    float*       Eb = g_att + (size_t)blockIdx.z * SS;

    int m0 = blockIdx.y * 64, n0 = blockIdx.x * 64;
    int tid = threadIdx.x;
    int tx = tid & 15, ty = tid >> 4;
    float acc[4][4] = {};

    for (int k0 = 0; k0 < F; k0 += 16) {
        int o  = k0 / S;
        int w0 = k0 % S;
        const float* Qo = Qb + (size_t)o * SS;
        const float* Ko = Kb + (size_t)o * SS;
#pragma unroll
        for (int i = 0; i < 4; ++i) {
            int idx = tid + i * 256;
            int k = idx & 15, m = idx >> 4;
            As[k][m] = Qo[(size_t)(m0 + m) * S + w0 + k];
            Bs[k][m] = Ko[(size_t)(n0 + m) * S + w0 + k];
        }
        __syncthreads();
#pragma unroll
        for (int k = 0; k < 16; ++k) {
            float a[4], bb[4];
#pragma unroll
            for (int i = 0; i < 4; ++i) a[i]  = As[k][ty * 4 + i];
#pragma unroll
            for (int j = 0; j < 4; ++j) bb[j] = Bs[k][tx * 4 + j];
#pragma unroll
            for (int i = 0; i < 4; ++i)
#pragma unroll
                for (int j = 0; j < 4; ++j) acc[i][j] += a[i] * bb[j];
        }
        __syncthreads();
    }
#pragma unroll
    for (int i = 0; i < 4; ++i)
#pragma unroll
        for (int j = 0; j < 4; ++j)
            Eb[(size_t)(m0 + ty * 4 + i) * S + n0 + tx * 4 + j] = acc[i][j];
}

// ---------------------------------------------------------------------------
// Row softmax in place on g_att: B*S rows of length S. blockDim = S.
// ---------------------------------------------------------------------------
__global__ void softmax_kernel(int S) {
    __shared__ float red[128];
    float* row = g_att + (size_t)blockIdx.x * S;
    int t = threadIdx.x;
    float v = row[t];
    red[t] = v;
    __syncthreads();
    for (int off = S >> 1; off > 0; off >>= 1) {
        if (t < off) red[t] = fmaxf(red[t], red[t + off]);
        __syncthreads();
    }
    float m = red[0];
    __syncthreads();
    float e = expf(v - m);
    red[t] = e;
    __syncthreads();
    for (int off = S >> 1; off > 0; off >>= 1) {
        if (t < off) red[t] += red[t + off];
        __syncthreads();
    }
    row[t] = e / red[0];
}

// ---------------------------------------------------------------------------
// Apply over W: out[b, m=(c*S+h), n=w] = 2*x + s * sum_v V[m,v]*A[w,v]
// V is rows [64,320) of QKV, contiguous [C*S, S]. grid = (S/64, C*S/64, B)
// ---------------------------------------------------------------------------
__global__ __launch_bounds__(256)
void apply_w_kernel(const float* __restrict__ x, float* __restrict__ out,
                    int S, const float* __restrict__ scalars, int br) {
    __shared__ float As[16][68];
    __shared__ float Bs[16][68];
    int SS = S * S;
    int b  = blockIdx.z;
    const float* Vb = g_qkv + (size_t)b * MROWS * SS + (size_t)64 * SS;
    const float* At = g_att + (size_t)b * SS;

    int m0 = blockIdx.y * 64, n0 = blockIdx.x * 64;
    int tid = threadIdx.x;
    int tx = tid & 15, ty = tid >> 4;
    float acc[4][4] = {};

    for (int k0 = 0; k0 < S; k0 += 16) {
#pragma unroll
        for (int i = 0; i < 4; ++i) {
            int idx = tid + i * 256;
            int k = idx & 15, m = idx >> 4;
            As[k][m] = Vb[(size_t)(m0 + m) * S + k0 + k];
            Bs[k][m] = At[(size_t)(n0 + m) * S + k0 + k];
        }
        __syncthreads();
#pragma unroll
        for (int k = 0; k < 16; ++k) {
            float a[4], bb[4];
#pragma unroll
            for (int i = 0; i < 4; ++i) a[i]  = As[k][ty * 4 + i];
#pragma unroll
            for (int j = 0; j < 4; ++j) bb[j] = Bs[k][tx * 4 + j];
#pragma unroll
            for (int i = 0; i < 4; ++i)
#pragma unroll
                for (int j = 0; j < 4; ++j) acc[i][j] += a[i] * bb[j];
        }
        __syncthreads();
    }
    float s = scalars[br];
#pragma unroll
    for (int i = 0; i < 4; ++i) {
        size_t base = (size_t)b * C_ * SS + (size_t)(m0 + ty * 4 + i) * S + n0 + tx * 4;
#pragma unroll
        for (int j = 0; j < 4; ++j)
            out[base + j] = 2.0f * x[base + j] + s * acc[i][j];
    }
}

// ---------------------------------------------------------------------------
// Apply over H: out[b,c,h,w] += s * sum_v A[h,v] * V[c,v,w]
// grid = (S/64, S/64, B*C)
// ---------------------------------------------------------------------------
__global__ __launch_bounds__(256)
void apply_h_kernel(float* __restrict__ out, int S,
                    const float* __restrict__ scalars, int br) {
    __shared__ float As[16][68];
    __shared__ float Bs[16][68];
    int SS = S * S;
    int bc = blockIdx.z;
    int b = bc / C_, c = bc % C_;
    const float* At = g_att + (size_t)b * SS;
    const float* Vc = g_qkv + (size_t)b * MROWS * SS + (size_t)(64 + c) * SS;

    int m0 = blockIdx.y * 64, n0 = blockIdx.x * 64;
    int tid = threadIdx.x;
    int tx = tid & 15, ty = tid >> 4;
    float acc[4][4] = {};

    for (int k0 = 0; k0 < S; k0 += 16) {
#pragma unroll
        for (int i = 0; i < 4; ++i) {
            int idx = tid + i * 256;
            {   // A[m][k] = At[(m0+m)*S + k0+k] -> As[k][m]
                int k = idx & 15, m = idx >> 4;
                As[k][m] = At[(size_t)(m0 + m) * S + k0 + k];
            }
            {   // B[k][n] = Vc[(k0+k)*S + n0+n] -> Bs[k][n] (coalesced)
                int n = idx & 63, k = idx >> 6;
                Bs[k][n] = Vc[(size_t)(k0 + k) * S + n0 + n];
            }
        }
        __syncthreads();
#pragma unroll
        for (int k = 0; k < 16; ++k) {
            float a[4], bb[4];
#pragma unroll
            for (int i = 0; i < 4; ++i) a[i]  = As[k][ty * 4 + i];
#pragma unroll
            for (int j = 0; j < 4; ++j) bb[j] = Bs[k][tx * 4 + j];
#pragma unroll
            for (int i = 0; i < 4; ++i)
#pragma unroll
                for (int j = 0; j < 4; ++j) acc[i][j] += a[i] * bb[j];
        }
        __syncthreads();
    }
    float s = scalars[br];
#pragma unroll
    for (int i = 0; i < 4; ++i) {
        size_t base = (size_t)b * C_ * SS + (size_t)c * SS
                    + (size_t)(m0 + ty * 4 + i) * S + n0 + tx * 4;
#pragma unroll
        for (int j = 0; j < 4; ++j)
            out[base + j] += s * acc[i][j];
    }
}

// ---------------------------------------------------------------------------
// Host-side orchestration
// ---------------------------------------------------------------------------
static void run_branch_pair(const float* x, int S, float* out,
                            int br_w, int br_h,
                            const float* qw, const float* qb,
                            const float* kw, const float* kb,
                            const float* vw, const float* vb,
                            const float* sc) {
    int SS = S * S;
    dim3 thr(256);

    // ---- over-W branch ----
    build_wc_kernel<<<(MROWS * C_ + 255) / 256, 256>>>(qw, qb, kw, kb, vw, vb, br_w);
    proj_kernel<<<dim3(SS / 64, MROWS / 64, B_), thr>>>(x, SS);
    logits_w_kernel<<<dim3(S / 64, S / 64, B_), thr>>>(S);
    softmax_kernel<<<B_ * S, S>>>(S);
    apply_w_kernel<<<dim3(S / 64, C_ * S / 64, B_), thr>>>(x, out, S, sc, br_w);

    // ---- over-H branch ----
    build_wc_kernel<<<(MROWS * C_ + 255) / 256, 256>>>(qw, qb, kw, kb, vw, vb, br_h);
    proj_kernel<<<dim3(SS / 64, MROWS / 64, B_), thr>>>(x, SS);
    logits_h_kernel<<<dim3(S / 64, S / 64, B_), thr>>>(S);
    softmax_kernel<<<B_ * S, S>>>(S);
    apply_h_kernel<<<dim3(S / 64, S / 64, B_ * C_), thr>>>(out, S, sc, br_h);
}

extern "C" void kernel_launch(void* const* d_in, const int* in_sizes, int n_in,
                              void* d_out, int out_size) {
    const float* tmap = (const float*)d_in[0];
    const float* smap = (const float*)d_in[1];
    const float* qw   = (const float*)d_in[2];
    const float* qb   = (const float*)d_in[3];
    const float* kw   = (const float*)d_in[4];
    const float* kb   = (const float*)d_in[5];
    const float* vw   = (const float*)d_in[6];
    const float* vb   = (const float*)d_in[7];
    const float* sc   = (const float*)d_in[8];

    float* tout = (float*)d_out;
    float* sout = tout + (size_t)B_ * C_ * 64 * 64;

    // template: branches 0 (over W), 2 (over H)
    run_branch_pair(tmap, 64, tout, 0, 2, qw, qb, kw, kb, vw, vb, sc);
    // scene: branches 1 (over W), 3 (over H)
    run_branch_pair(smap, 128, sout, 1, 3, qw, qb, kw, kb, vw, vb, sc);
}

// round 10
// speedup vs baseline: 1.4505x; 1.4498x over previous
#include <cuda_runtime.h>
#include <cstdint>

// ===========================================================================
// PAM module on GB300 (compiled at base sm_103 target -> tcgen05 unavailable).
// Engine: mma.sync m16n8k8 tf32 tensor-core GEMMs for V-proj / apply-W /
// apply-H; fp32 SIMT for Q,K projection + logits (precision-critical path).
// B=16, C=256, C8=32. Template 64x64, scene 128x128.
// ===========================================================================

#define B_  16
#define C_  256
#define MR  320   // 32 q + 32 k + 256 v

// --------------------------- device scratch --------------------------------
__device__ float g_qkv[(size_t)B_ * MR * 128 * 128];   // 335 MB
__device__ float g_xt [(size_t)B_ * C_ * 128 * 128];   // 268 MB (Xt, later Vt)
__device__ float g_att[(size_t)B_ * 128 * 128];
__device__ float g_wc [MR * C_];
__device__ float g_bc [MR];

// --------------------------- PTX helpers -----------------------------------
__device__ __forceinline__ void cp16(void* dst, const void* src) {
    uint32_t d = (uint32_t)__cvta_generic_to_shared(dst);
    asm volatile("cp.async.cg.shared.global [%0], [%1], 16;" :: "r"(d), "l"(src));
}
__device__ __forceinline__ void cp_commit() {
    asm volatile("cp.async.commit_group;" ::: "memory");
}
__device__ __forceinline__ void mma_tf32(float* c, const uint32_t* a, const uint32_t* b) {
    asm volatile("mma.sync.aligned.m16n8k8.row.col.f32.tf32.tf32.f32 "
        "{%0,%1,%2,%3}, {%4,%5,%6,%7}, {%8,%9}, {%0,%1,%2,%3};"
        : "+f"(c[0]), "+f"(c[1]), "+f"(c[2]), "+f"(c[3])
        : "r"(a[0]), "r"(a[1]), "r"(a[2]), "r"(a[3]), "r"(b[0]), "r"(b[1]));
}

// ---------------------------------------------------------------------------
// Build stacked weight [320,256] and bias [320] for one branch.
// ---------------------------------------------------------------------------
__global__ void build_wc_kernel(const float* __restrict__ qw, const float* __restrict__ qb,
                                const float* __restrict__ kw, const float* __restrict__ kb,
                                const float* __restrict__ vw, const float* __restrict__ vb,
                                int br) {
    int i = blockIdx.x * blockDim.x + threadIdx.x;
    if (i < MR * C_) {
        int m = i / C_, k = i % C_;
        float val;
        if (m < 32)       val = qw[(size_t)br * 32 * C_ + m * C_ + k];
        else if (m < 64)  val = kw[(size_t)br * 32 * C_ + (m - 32) * C_ + k];
        else              val = vw[(size_t)br * C_ * C_ + (m - 64) * C_ + k];
        g_wc[i] = val;
    }
    if (i < MR) {
        g_bc[i] = (i < 32) ? qb[br * 32 + i]
                : (i < 64) ? kb[br * 32 + i - 32]
                           : vb[br * C_ + i - 64];
    }
}

// ---------------------------------------------------------------------------
// Batched 32x32 tiled transpose: dst[z][c][r] = src[z][r][c].
// ---------------------------------------------------------------------------
__global__ void transpose_kernel(const float* __restrict__ src, float* __restrict__ dst,
                                 int R, int Cc, int zdiv,
                                 size_t s1, size_t s2, size_t d1, size_t d2) {
    __shared__ float t[32][33];
    int z = blockIdx.z;
    src += (size_t)(z / zdiv) * s1 + (size_t)(z % zdiv) * s2;
    dst += (size_t)(z / zdiv) * d1 + (size_t)(z % zdiv) * d2;
    int x0 = blockIdx.x * 32, y0 = blockIdx.y * 32;
    int tx = threadIdx.x, ty = threadIdx.y;
#pragma unroll
    for (int j = 0; j < 32; j += 8)
        t[ty + j][tx] = src[(size_t)(y0 + ty + j) * Cc + x0 + tx];
    __syncthreads();
#pragma unroll
    for (int j = 0; j < 32; j += 8)
        dst[(size_t)(x0 + ty + j) * R + y0 + tx] = t[tx][ty + j];
}

// ---------------------------------------------------------------------------
// Tensor-core GEMM: D[z][m][n] = sum_k A[m][k] * B[n][k]  (+epilogue)
//   block tile 128 x NT, K tiled by 32; cp.async double buffer.
//   A addr: A + (z/aZ)*aB + m*aR ; B addr: B + z*bB + n*bR (both k-contig).
//   mode: 0 = +bias[m]; 2 = out = 2*x + s*d; 3 = out += s*d
// ---------------------------------------------------------------------------
template<int NT>
__global__ __launch_bounds__(256)
void mma_gemm(const float* __restrict__ A, size_t aR, size_t aB, int aZ,
              const float* __restrict__ Bp, size_t bR, size_t bB,
              float* __restrict__ D, size_t dR, size_t dB,
              int K, int Mvalid, int mode,
              const float* __restrict__ bias, const float* __restrict__ xres,
              const float* __restrict__ scal, int br) {
    extern __shared__ float sm[];
    float* Asm[2] = { sm, sm + 128 * 36 };
    float* Bsm[2] = { sm + 2 * 128 * 36, sm + 2 * 128 * 36 + NT * 36 };

    int tid = threadIdx.x, lane = tid & 31, wid = tid >> 5;
    int z = blockIdx.z;
    int m0b = blockIdx.y * 128, n0b = blockIdx.x * NT;

    const float* Ag = A + (size_t)(z / aZ) * aB + (size_t)m0b * aR;
    const float* Bg = Bp + (size_t)z * bB + (size_t)n0b * bR;

    auto fill = [&](int buf, int k0) {
#pragma unroll
        for (int it = 0; it < 4; ++it) {            // A: 128 rows x 32 k
            int i = tid + it * 256;
            int r = i >> 3, c = (i & 7) << 2;
            cp16(&Asm[buf][r * 36 + c], Ag + (size_t)r * aR + k0 + c);
        }
#pragma unroll
        for (int it = 0; it < NT / 32; ++it) {      // B: NT rows x 32 k
            int i = tid + it * 256;
            int r = i >> 3, c = (i & 7) << 2;
            cp16(&Bsm[buf][r * 36 + c], Bg + (size_t)r * bR + k0 + c);
        }
        cp_commit();
    };

    constexpr int WNW = NT / 32;     // warps along n (4 or 2)
    constexpr int MI  = NT / 32;     // m16-tiles per warp (4 or 2)
    int wn = wid % WNW, wm = wid / WNW;
    int wm0 = wm * (MI * 16), wn0 = wn * 32;

    float acc[MI][4][4];
#pragma unroll
    for (int a = 0; a < MI; ++a)
#pragma unroll
        for (int b = 0; b < 4; ++b)
#pragma unroll
            for (int c = 0; c < 4; ++c) acc[a][b][c] = 0.f;

    int nkt = K >> 5;
    fill(0, 0);
    for (int kt = 0; kt < nkt; ++kt) {
        int buf = kt & 1;
        if (kt + 1 < nkt) {
            fill(buf ^ 1, (kt + 1) << 5);
            asm volatile("cp.async.wait_group 1;" ::: "memory");
        } else {
            asm volatile("cp.async.wait_group 0;" ::: "memory");
        }
        __syncthreads();
        const float* At = Asm[buf];
        const float* Bt = Bsm[buf];
#pragma unroll
        for (int ks = 0; ks < 4; ++ks) {
            uint32_t af[MI][4], bf[4][2];
            int kk = ks * 8 + (lane & 3);
#pragma unroll
            for (int mi = 0; mi < MI; ++mi) {
                int m = wm0 + mi * 16 + (lane >> 2);
                af[mi][0] = __float_as_uint(At[m * 36 + kk]);
                af[mi][1] = __float_as_uint(At[(m + 8) * 36 + kk]);
                af[mi][2] = __float_as_uint(At[m * 36 + kk + 4]);
                af[mi][3] = __float_as_uint(At[(m + 8) * 36 + kk + 4]);
            }
#pragma unroll
            for (int ni = 0; ni < 4; ++ni) {
                int n = wn0 + ni * 8 + (lane >> 2);
                bf[ni][0] = __float_as_uint(Bt[n * 36 + kk]);
                bf[ni][1] = __float_as_uint(Bt[n * 36 + kk + 4]);
            }
#pragma unroll
            for (int mi = 0; mi < MI; ++mi)
#pragma unroll
                for (int ni = 0; ni < 4; ++ni)
                    mma_tf32(acc[mi][ni], af[mi], bf[ni]);
        }
        __syncthreads();
    }

    // Epilogue straight from accumulators (coalesced float2 per thread)
    float s = (mode >= 2) ? scal[br] : 0.f;
#pragma unroll
    for (int mi = 0; mi < MI; ++mi)
#pragma unroll
        for (int ni = 0; ni < 4; ++ni)
#pragma unroll
            for (int h = 0; h < 2; ++h) {
                int row = m0b + wm0 + mi * 16 + (lane >> 2) + h * 8;
                int col = n0b + wn0 + ni * 8 + (lane & 3) * 2;
                if (row < Mvalid) {
                    size_t off = (size_t)z * dB + (size_t)row * dR + col;
                    float d0 = acc[mi][ni][h * 2], d1 = acc[mi][ni][h * 2 + 1];
                    float2 v;
                    if (mode == 0) {
                        float bi = bias[row];
                        v = make_float2(d0 + bi, d1 + bi);
                    } else if (mode == 2) {
                        float2 x2 = *(const float2*)(xres + off);
                        v = make_float2(2.f * x2.x + s * d0, 2.f * x2.y + s * d1);
                    } else {
                        float2 o = *(const float2*)(D + off);
                        v = make_float2(o.x + s * d0, o.y + s * d1);
                    }
                    *(float2*)(D + off) = v;
                }
            }
}

// ---------------------------------------------------------------------------
// fp32 SIMT: Q,K projection (rows 0..63) -- precision-critical.
// Out[b,m,n] = sum_k Wc[m,k] * X[b,k,n] + bc[m].  grid = (HW/64, 1, B)
// ---------------------------------------------------------------------------
__global__ __launch_bounds__(256)
void proj_kernel(const float* __restrict__ x, int HW) {
    __shared__ float As[16][68];
    __shared__ float Bs[16][68];
    int b  = blockIdx.z;
    int m0 = blockIdx.y * 64;
    int n0 = blockIdx.x * 64;
    const float* Xb = x + (size_t)b * C_ * HW;
    float*       Ob = g_qkv + (size_t)b * MR * HW;

    int tid = threadIdx.x, tx = tid & 15, ty = tid >> 4;
    float acc[4][4] = {};

    for (int k0 = 0; k0 < C_; k0 += 16) {
#pragma unroll
        for (int i = 0; i < 4; ++i) {
            int idx = tid + i * 256;
            int m = idx >> 4, k = idx & 15;
            As[k][m] = g_wc[(m0 + m) * C_ + k0 + k];
        }
#pragma unroll
        for (int i = 0; i < 4; ++i) {
            int idx = tid + i * 256;
            int n = idx & 63, k = idx >> 6;
            Bs[k][n] = Xb[(size_t)(k0 + k) * HW + n0 + n];
        }
        __syncthreads();
#pragma unroll
        for (int k = 0; k < 16; ++k) {
            float a[4], bb[4];
#pragma unroll
            for (int i = 0; i < 4; ++i) a[i]  = As[k][ty * 4 + i];
#pragma unroll
            for (int j = 0; j < 4; ++j) bb[j] = Bs[k][tx * 4 + j];
#pragma unroll
            for (int i = 0; i < 4; ++i)
#pragma unroll
                for (int j = 0; j < 4; ++j) acc[i][j] += a[i] * bb[j];
        }
        __syncthreads();
    }
#pragma unroll
    for (int i = 0; i < 4; ++i) {
        int m = m0 + ty * 4 + i;
        float bias = g_bc[m];
#pragma unroll
        for (int j = 0; j < 4; ++j)
            Ob[(size_t)m * HW + n0 + tx * 4 + j] = acc[i][j] + bias;
    }
}

// ---------------------------------------------------------------------------
// fp32 SIMT logits (both maps): over-W and over-H.
// ---------------------------------------------------------------------------
__global__ __launch_bounds__(256)
void logits_w_kernel(int S) {
    __shared__ float As[16][68];
    __shared__ float Bs[16][68];
    int SS = S * S, F = 32 * S;
    const float* Qb = g_qkv + (size_t)blockIdx.z * MR * SS;
    const float* Kb = Qb + (size_t)32 * SS;
    float* Eb = g_att + (size_t)blockIdx.z * SS;
    int m0 = blockIdx.y * 64, n0 = blockIdx.x * 64;
    int tid = threadIdx.x, tx = tid & 15, ty = tid >> 4;
    float acc[4][4] = {};
    for (int k0 = 0; k0 < F; k0 += 16) {
#pragma unroll
        for (int i = 0; i < 4; ++i) {
            int idx = tid + i * 256;
            int n = idx & 63, k = idx >> 6;
            As[k][n] = Qb[(size_t)(k0 + k) * S + m0 + n];
            Bs[k][n] = Kb[(size_t)(k0 + k) * S + n0 + n];
        }
        __syncthreads();
#pragma unroll
        for (int k = 0; k < 16; ++k) {
            float a[4], bb[4];
#pragma unroll
            for (int i = 0; i < 4; ++i) a[i] = As[k][ty * 4 + i];
#pragma unroll
            for (int j = 0; j < 4; ++j) bb[j] = Bs[k][tx * 4 + j];
#pragma unroll
            for (int i = 0; i < 4; ++i)
#pragma unroll
                for (int j = 0; j < 4; ++j) acc[i][j] += a[i] * bb[j];
        }
        __syncthreads();
    }
#pragma unroll
    for (int i = 0; i < 4; ++i)
#pragma unroll
        for (int j = 0; j < 4; ++j)
            Eb[(size_t)(m0 + ty * 4 + i) * S + n0 + tx * 4 + j] = acc[i][j];
}

__global__ __launch_bounds__(256)
void logits_h_kernel(int S) {
    __shared__ float As[16][68];
    __shared__ float Bs[16][68];
    int SS = S * S, F = 32 * S;
    const float* Qb = g_qkv + (size_t)blockIdx.z * MR * SS;
    const float* Kb = Qb + (size_t)32 * SS;
    float* Eb = g_att + (size_t)blockIdx.z * SS;
    int m0 = blockIdx.y * 64, n0 = blockIdx.x * 64;
    int tid = threadIdx.x, tx = tid & 15, ty = tid >> 4;
    float acc[4][4] = {};
    for (int k0 = 0; k0 < F; k0 += 16) {
        int o = k0 / S, w0 = k0 % S;
        const float* Qo = Qb + (size_t)o * SS;
        const float* Ko = Kb + (size_t)o * SS;
#pragma unroll
        for (int i = 0; i < 4; ++i) {
            int idx = tid + i * 256;
            int k = idx & 15, m = idx >> 4;
            As[k][m] = Qo[(size_t)(m0 + m) * S + w0 + k];
            Bs[k][m] = Ko[(size_t)(n0 + m) * S + w0 + k];
        }
        __syncthreads();
#pragma unroll
        for (int k = 0; k < 16; ++k) {
            float a[4], bb[4];
#pragma unroll
            for (int i = 0; i < 4; ++i) a[i] = As[k][ty * 4 + i];
#pragma unroll
            for (int j = 0; j < 4; ++j) bb[j] = Bs[k][tx * 4 + j];
#pragma unroll
            for (int i = 0; i < 4; ++i)
#pragma unroll
                for (int j = 0; j < 4; ++j) acc[i][j] += a[i] * bb[j];
        }
        __syncthreads();
    }
#pragma unroll
    for (int i = 0; i < 4; ++i)
#pragma unroll
        for (int j = 0; j < 4; ++j)
            Eb[(size_t)(m0 + ty * 4 + i) * S + n0 + tx * 4 + j] = acc[i][j];
}

__global__ void softmax_kernel(int S) {
    __shared__ float red[128];
    float* row = g_att + (size_t)blockIdx.x * S;
    int t = threadIdx.x;
    float v = row[t];
    red[t] = v;
    __syncthreads();
    for (int off = S >> 1; off > 0; off >>= 1) {
        if (t < off) red[t] = fmaxf(red[t], red[t + off]);
        __syncthreads();
    }
    float m = red[0];
    __syncthreads();
    float e = expf(v - m);
    red[t] = e;
    __syncthreads();
    for (int off = S >> 1; off > 0; off >>= 1) {
        if (t < off) red[t] += red[t + off];
        __syncthreads();
    }
    row[t] = e / red[0];
}

// ---------------------------------------------------------------------------
// Host orchestration
// ---------------------------------------------------------------------------
static void process_map(const float* x, int S, float* out, int brw, int brh,
                        const float* qw, const float* qb, const float* kw, const float* kb,
                        const float* vw, const float* vb, const float* sc,
                        float* qkv, float* xt, float* att, float* wc, float* bc) {
    const size_t SS = (size_t)S * S;
    const bool big = (S == 128);
    dim3 t32(32, 8);

    // X^T (pixel-major [SS][C]) for QKV projection B operand
    transpose_kernel<<<dim3(SS / 32, C_ / 32, B_), t32>>>(x, xt, C_, (int)SS,
                                                          1, C_ * SS, 0, C_ * SS, 0);

    for (int pass = 0; pass < 2; ++pass) {
        int br = pass ? brh : brw;
        build_wc_kernel<<<(MR * C_ + 255) / 256, 256>>>(qw, qb, kw, kb, vw, vb, br);
        // Q,K rows 0..63 in fp32 (precision for logits)
        proj_kernel<<<dim3(SS / 64, 1, B_), 256>>>(x, (int)SS);
        // V rows 64..319 via tensor cores
        mma_gemm<128><<<dim3(SS / 128, 2, B_), 256, 73728>>>(
            wc + 64 * C_, C_, 0, 1,
            xt, C_, C_ * SS,
            qkv + 64 * SS, SS, (size_t)MR * SS,
            C_, 256, 0, bc + 64, nullptr, sc, br);

        if (pass == 0) logits_w_kernel<<<dim3(S / 64, S / 64, B_), 256>>>(S);
        else           logits_h_kernel<<<dim3(S / 64, S / 64, B_), 256>>>(S);
        softmax_kernel<<<B_ * S, S>>>(S);

        if (pass == 0) {
            // apply-W: out = 2x + s * V @ A^T   (A operand rows = V[(c,h)][v])
            if (big)
                mma_gemm<128><<<dim3(1, C_ * S / 128, B_), 256, 73728>>>(
                    qkv + 64 * SS, S, (size_t)MR * SS, 1,
                    att, S, SS,
                    out, S, (size_t)C_ * SS,
                    S, C_ * S, 2, nullptr, x, sc, br);
            else
                mma_gemm<64><<<dim3(1, C_ * S / 128, B_), 256, 55296>>>(
                    qkv + 64 * SS, S, (size_t)MR * SS, 1,
                    att, S, SS,
                    out, S, (size_t)C_ * SS,
                    S, C_ * S, 2, nullptr, x, sc, br);
        } else {
            // spatial transpose of V into xt (Xt no longer needed)
            transpose_kernel<<<dim3(S / 32, S / 32, B_ * C_), t32>>>(
                qkv + 64 * SS, xt, S, S, C_, (size_t)MR * SS, SS, (size_t)C_ * SS, SS);
            // apply-H: out += s * A @ V   (B operand rows = Vt[w][v])
            if (big)
                mma_gemm<128><<<dim3(1, 1, B_ * C_), 256, 73728>>>(
                    att, S, SS, C_,
                    xt, S, SS,
                    out, S, SS,
                    S, S, 3, nullptr, nullptr, sc, br);
            else
                mma_gemm<64><<<dim3(1, 1, B_ * C_), 256, 55296>>>(
                    att, S, SS, C_,
                    xt, S, SS,
                    out, S, SS,
                    S, S, 3, nullptr, nullptr, sc, br);
        }
    }
}

extern "C" void kernel_launch(void* const* d_in, const int* in_sizes, int n_in,
                              void* d_out, int out_size) {
    const float* tmap = (const float*)d_in[0];
    const float* smap = (const float*)d_in[1];
    const float* qw   = (const float*)d_in[2];
    const float* qb   = (const float*)d_in[3];
    const float* kw   = (const float*)d_in[4];
    const float* kb   = (const float*)d_in[5];
    const float* vw   = (const float*)d_in[6];
    const float* vb   = (const float*)d_in[7];
    const float* sc   = (const float*)d_in[8];

    cudaFuncSetAttribute(mma_gemm<128>, cudaFuncAttributeMaxDynamicSharedMemorySize, 73728);
    cudaFuncSetAttribute(mma_gemm<64>,  cudaFuncAttributeMaxDynamicSharedMemorySize, 55296);

    void *p_qkv, *p_xt, *p_att, *p_wc, *p_bc;
    cudaGetSymbolAddress(&p_qkv, g_qkv);
    cudaGetSymbolAddress(&p_xt,  g_xt);
    cudaGetSymbolAddress(&p_att, g_att);
    cudaGetSymbolAddress(&p_wc,  g_wc);
    cudaGetSymbolAddress(&p_bc,  g_bc);

    float* tout = (float*)d_out;
    float* sout = tout + (size_t)B_ * C_ * 64 * 64;

    process_map(tmap, 64,  tout, 0, 2, qw, qb, kw, kb, vw, vb, sc,
                (float*)p_qkv, (float*)p_xt, (float*)p_att, (float*)p_wc, (float*)p_bc);
    process_map(smap, 128, sout, 1, 3, qw, qb, kw, kb, vw, vb, sc,
                (float*)p_qkv, (float*)p_xt, (float*)p_att, (float*)p_wc, (float*)p_bc);
}

// round 11
// speedup vs baseline: 1.4658x; 1.0105x over previous
#include <cuda_runtime.h>
#include <cstdint>

// ===========================================================================
// PAM module on GB300 (compiled at base sm_103 target -> tcgen05 unavailable).
// Engine: mma.sync m16n8k8 tf32 tensor-core GEMMs for V-proj / apply-W /
// apply-H; fp32 SIMT for Q,K projection + logits (precision-critical path).
// B=16, C=256, C8=32. Template 64x64, scene 128x128.
// ===========================================================================

#define B_  16
#define C_  256
#define MR  320   // 32 q + 32 k + 256 v

// --------------------------- device scratch --------------------------------
__device__ float g_qkv[(size_t)B_ * MR * 128 * 128];   // 335 MB
__device__ float g_xt [(size_t)B_ * C_ * 128 * 128];   // 268 MB (Xt, later Vt)
__device__ float g_att[(size_t)B_ * 128 * 128];
__device__ float g_wc [MR * C_];
__device__ float g_bc [MR];

// --------------------------- PTX helpers -----------------------------------
__device__ __forceinline__ void cp16(void* dst, const void* src) {
    uint32_t d = (uint32_t)__cvta_generic_to_shared(dst);
    asm volatile("cp.async.cg.shared.global [%0], [%1], 16;" :: "r"(d), "l"(src));
}
__device__ __forceinline__ void cp_commit() {
    asm volatile("cp.async.commit_group;" ::: "memory");
}
__device__ __forceinline__ void mma_tf32(float* c, const uint32_t* a, const uint32_t* b) {
    asm volatile("mma.sync.aligned.m16n8k8.row.col.f32.tf32.tf32.f32 "
        "{%0,%1,%2,%3}, {%4,%5,%6,%7}, {%8,%9}, {%0,%1,%2,%3};"
        : "+f"(c[0]), "+f"(c[1]), "+f"(c[2]), "+f"(c[3])
        : "r"(a[0]), "r"(a[1]), "r"(a[2]), "r"(a[3]), "r"(b[0]), "r"(b[1]));
}

// ---------------------------------------------------------------------------
// Build stacked weight [320,256] and bias [320] for one branch.
// ---------------------------------------------------------------------------
__global__ void build_wc_kernel(const float* __restrict__ qw, const float* __restrict__ qb,
                                const float* __restrict__ kw, const float* __restrict__ kb,
                                const float* __restrict__ vw, const float* __restrict__ vb,
                                int br) {
    int i = blockIdx.x * blockDim.x + threadIdx.x;
    if (i < MR * C_) {
        int m = i / C_, k = i % C_;
        float val;
        if (m < 32)       val = qw[(size_t)br * 32 * C_ + m * C_ + k];
        else if (m < 64)  val = kw[(size_t)br * 32 * C_ + (m - 32) * C_ + k];
        else              val = vw[(size_t)br * C_ * C_ + (m - 64) * C_ + k];
        g_wc[i] = val;
    }
    if (i < MR) {
        g_bc[i] = (i < 32) ? qb[br * 32 + i]
                : (i < 64) ? kb[br * 32 + i - 32]
                           : vb[br * C_ + i - 64];
    }
}

// ---------------------------------------------------------------------------
// Batched 32x32 tiled transpose: dst[z][c][r] = src[z][r][c].
// ---------------------------------------------------------------------------
__global__ void transpose_kernel(const float* __restrict__ src, float* __restrict__ dst,
                                 int R, int Cc, int zdiv,
                                 size_t s1, size_t s2, size_t d1, size_t d2) {
    __shared__ float t[32][33];
    int z = blockIdx.z;
    src += (size_t)(z / zdiv) * s1 + (size_t)(z % zdiv) * s2;
    dst += (size_t)(z / zdiv) * d1 + (size_t)(z % zdiv) * d2;
    int x0 = blockIdx.x * 32, y0 = blockIdx.y * 32;
    int tx = threadIdx.x, ty = threadIdx.y;
#pragma unroll
    for (int j = 0; j < 32; j += 8)
        t[ty + j][tx] = src[(size_t)(y0 + ty + j) * Cc + x0 + tx];
    __syncthreads();
#pragma unroll
    for (int j = 0; j < 32; j += 8)
        dst[(size_t)(x0 + ty + j) * R + y0 + tx] = t[tx][ty + j];
}

// ---------------------------------------------------------------------------
// Tensor-core GEMM: D[z][m][n] = sum_k A[m][k] * B[n][k]  (+epilogue)
//   block tile 128 x NT, K tiled by 32; cp.async double buffer.
//   A addr: A + (z/aZ)*aB + m*aR ; B addr: B + z*bB + n*bR (both k-contig).
//   mode: 0 = +bias[m]; 2 = out = 2*x + s*d; 3 = out += s*d
// ---------------------------------------------------------------------------
template<int NT>
__global__ __launch_bounds__(256)
void mma_gemm(const float* __restrict__ A, size_t aR, size_t aB, int aZ,
              const float* __restrict__ Bp, size_t bR, size_t bB,
              float* __restrict__ D, size_t dR, size_t dB,
              int K, int Mvalid, int mode,
              const float* __restrict__ bias, const float* __restrict__ xres,
              const float* __restrict__ scal, int br) {
    extern __shared__ float sm[];
    float* Asm[2] = { sm, sm + 128 * 36 };
    float* Bsm[2] = { sm + 2 * 128 * 36, sm + 2 * 128 * 36 + NT * 36 };

    int tid = threadIdx.x, lane = tid & 31, wid = tid >> 5;
    int z = blockIdx.z;
    int m0b = blockIdx.y * 128, n0b = blockIdx.x * NT;

    const float* Ag = A + (size_t)(z / aZ) * aB + (size_t)m0b * aR;
    const float* Bg = Bp + (size_t)z * bB + (size_t)n0b * bR;

    auto fill = [&](int buf, int k0) {
#pragma unroll
        for (int it = 0; it < 4; ++it) {            // A: 128 rows x 32 k
            int i = tid + it * 256;
            int r = i >> 3, c = (i & 7) << 2;
            cp16(&Asm[buf][r * 36 + c], Ag + (size_t)r * aR + k0 + c);
        }
#pragma unroll
        for (int it = 0; it < NT / 32; ++it) {      // B: NT rows x 32 k
            int i = tid + it * 256;
            int r = i >> 3, c = (i & 7) << 2;
            cp16(&Bsm[buf][r * 36 + c], Bg + (size_t)r * bR + k0 + c);
        }
        cp_commit();
    };

    constexpr int WNW = NT / 32;     // warps along n (4 or 2)
    constexpr int MI  = NT / 32;     // m16-tiles per warp (4 or 2)
    int wn = wid % WNW, wm = wid / WNW;
    int wm0 = wm * (MI * 16), wn0 = wn * 32;

    float acc[MI][4][4];
#pragma unroll
    for (int a = 0; a < MI; ++a)
#pragma unroll
        for (int b = 0; b < 4; ++b)
#pragma unroll
            for (int c = 0; c < 4; ++c) acc[a][b][c] = 0.f;

    int nkt = K >> 5;
    fill(0, 0);
    for (int kt = 0; kt < nkt; ++kt) {
        int buf = kt & 1;
        if (kt + 1 < nkt) {
            fill(buf ^ 1, (kt + 1) << 5);
            asm volatile("cp.async.wait_group 1;" ::: "memory");
        } else {
            asm volatile("cp.async.wait_group 0;" ::: "memory");
        }
        __syncthreads();
        const float* At = Asm[buf];
        const float* Bt = Bsm[buf];
#pragma unroll
        for (int ks = 0; ks < 4; ++ks) {
            uint32_t af[MI][4], bf[4][2];
            int kk = ks * 8 + (lane & 3);
#pragma unroll
            for (int mi = 0; mi < MI; ++mi) {
                int m = wm0 + mi * 16 + (lane >> 2);
                af[mi][0] = __float_as_uint(At[m * 36 + kk]);
                af[mi][1] = __float_as_uint(At[(m + 8) * 36 + kk]);
                af[mi][2] = __float_as_uint(At[m * 36 + kk + 4]);
                af[mi][3] = __float_as_uint(At[(m + 8) * 36 + kk + 4]);
            }
#pragma unroll
            for (int ni = 0; ni < 4; ++ni) {
                int n = wn0 + ni * 8 + (lane >> 2);
                bf[ni][0] = __float_as_uint(Bt[n * 36 + kk]);
                bf[ni][1] = __float_as_uint(Bt[n * 36 + kk + 4]);
            }
#pragma unroll
            for (int mi = 0; mi < MI; ++mi)
#pragma unroll
                for (int ni = 0; ni < 4; ++ni)
                    mma_tf32(acc[mi][ni], af[mi], bf[ni]);
        }
        __syncthreads();
    }

    // Epilogue straight from accumulators (coalesced float2 per thread)
    float s = (mode >= 2) ? scal[br] : 0.f;
#pragma unroll
    for (int mi = 0; mi < MI; ++mi)
#pragma unroll
        for (int ni = 0; ni < 4; ++ni)
#pragma unroll
            for (int h = 0; h < 2; ++h) {
                int row = m0b + wm0 + mi * 16 + (lane >> 2) + h * 8;
                int col = n0b + wn0 + ni * 8 + (lane & 3) * 2;
                if (row < Mvalid) {
                    size_t off = (size_t)z * dB + (size_t)row * dR + col;
                    float d0 = acc[mi][ni][h * 2], d1 = acc[mi][ni][h * 2 + 1];
                    float2 v;
                    if (mode == 0) {
                        float bi = bias[row];
                        v = make_float2(d0 + bi, d1 + bi);
                    } else if (mode == 2) {
                        float2 x2 = *(const float2*)(xres + off);
                        v = make_float2(2.f * x2.x + s * d0, 2.f * x2.y + s * d1);
                    } else {
                        float2 o = *(const float2*)(D + off);
                        v = make_float2(o.x + s * d0, o.y + s * d1);
                    }
                    *(float2*)(D + off) = v;
                }
            }
}

// ---------------------------------------------------------------------------
// fp32 SIMT: Q,K projection (rows 0..63) -- precision-critical.
// Out[b,m,n] = sum_k Wc[m,k] * X[b,k,n] + bc[m].  grid = (HW/64, 1, B)
// ---------------------------------------------------------------------------
__global__ __launch_bounds__(256)
void proj_kernel(const float* __restrict__ x, int HW) {
    __shared__ float As[16][68];
    __shared__ float Bs[16][68];
    int b  = blockIdx.z;
    int m0 = blockIdx.y * 64;
    int n0 = blockIdx.x * 64;
    const float* Xb = x + (size_t)b * C_ * HW;
    float*       Ob = g_qkv + (size_t)b * MR * HW;

    int tid = threadIdx.x, tx = tid & 15, ty = tid >> 4;
    float acc[4][4] = {};

    for (int k0 = 0; k0 < C_; k0 += 16) {
#pragma unroll
        for (int i = 0; i < 4; ++i) {
            int idx = tid + i * 256;
            int m = idx >> 4, k = idx & 15;
            As[k][m] = g_wc[(m0 + m) * C_ + k0 + k];
        }
#pragma unroll
        for (int i = 0; i < 4; ++i) {
            int idx = tid + i * 256;
            int n = idx & 63, k = idx >> 6;
            Bs[k][n] = Xb[(size_t)(k0 + k) * HW + n0 + n];
        }
        __syncthreads();
#pragma unroll
        for (int k = 0; k < 16; ++k) {
            float a[4], bb[4];
#pragma unroll
            for (int i = 0; i < 4; ++i) a[i]  = As[k][ty * 4 + i];
#pragma unroll
            for (int j = 0; j < 4; ++j) bb[j] = Bs[k][tx * 4 + j];
#pragma unroll
            for (int i = 0; i < 4; ++i)
#pragma unroll
                for (int j = 0; j < 4; ++j) acc[i][j] += a[i] * bb[j];
        }
        __syncthreads();
    }
#pragma unroll
    for (int i = 0; i < 4; ++i) {
        int m = m0 + ty * 4 + i;
        float bias = g_bc[m];
#pragma unroll
        for (int j = 0; j < 4; ++j)
            Ob[(size_t)m * HW + n0 + tx * 4 + j] = acc[i][j] + bias;
    }
}

// ---------------------------------------------------------------------------
// fp32 SIMT logits (both maps): over-W and over-H.
// ---------------------------------------------------------------------------
__global__ __launch_bounds__(256)
void logits_w_kernel(int S) {
    __shared__ float As[16][68];
    __shared__ float Bs[16][68];
    int SS = S * S, F = 32 * S;
    const float* Qb = g_qkv + (size_t)blockIdx.z * MR * SS;
    const float* Kb = Qb + (size_t)32 * SS;
    float* Eb = g_att + (size_t)blockIdx.z * SS;
    int m0 = blockIdx.y * 64, n0 = blockIdx.x * 64;
    int tid = threadIdx.x, tx = tid & 15, ty = tid >> 4;
    float acc[4][4] = {};
    for (int k0 = 0; k0 < F; k0 += 16) {
#pragma unroll
        for (int i = 0; i < 4; ++i) {
            int idx = tid + i * 256;
            int n = idx & 63, k = idx >> 6;
            As[k][n] = Qb[(size_t)(k0 + k) * S + m0 + n];
            Bs[k][n] = Kb[(size_t)(k0 + k) * S + n0 + n];
        }
        __syncthreads();
#pragma unroll
        for (int k = 0; k < 16; ++k) {
            float a[4], bb[4];
#pragma unroll
            for (int i = 0; i < 4; ++i) a[i] = As[k][ty * 4 + i];
#pragma unroll
            for (int j = 0; j < 4; ++j) bb[j] = Bs[k][tx * 4 + j];
#pragma unroll
            for (int i = 0; i < 4; ++i)
#pragma unroll
                for (int j = 0; j < 4; ++j) acc[i][j] += a[i] * bb[j];
        }
        __syncthreads();
    }
#pragma unroll
    for (int i = 0; i < 4; ++i)
#pragma unroll
        for (int j = 0; j < 4; ++j)
            Eb[(size_t)(m0 + ty * 4 + i) * S + n0 + tx * 4 + j] = acc[i][j];
}

__global__ __launch_bounds__(256)
void logits_h_kernel(int S) {
    __shared__ float As[16][68];
    __shared__ float Bs[16][68];
    int SS = S * S, F = 32 * S;
    const float* Qb = g_qkv + (size_t)blockIdx.z * MR * SS;
    const float* Kb = Qb + (size_t)32 * SS;
    float* Eb = g_att + (size_t)blockIdx.z * SS;
    int m0 = blockIdx.y * 64, n0 = blockIdx.x * 64;
    int tid = threadIdx.x, tx = tid & 15, ty = tid >> 4;
    float acc[4][4] = {};
    for (int k0 = 0; k0 < F; k0 += 16) {
        int o = k0 / S, w0 = k0 % S;
        const float* Qo = Qb + (size_t)o * SS;
        const float* Ko = Kb + (size_t)o * SS;
#pragma unroll
        for (int i = 0; i < 4; ++i) {
            int idx = tid + i * 256;
            int k = idx & 15, m = idx >> 4;
            As[k][m] = Qo[(size_t)(m0 + m) * S + w0 + k];
            Bs[k][m] = Ko[(size_t)(n0 + m) * S + w0 + k];
        }
        __syncthreads();
#pragma unroll
        for (int k = 0; k < 16; ++k) {
            float a[4], bb[4];
#pragma unroll
            for (int i = 0; i < 4; ++i) a[i] = As[k][ty * 4 + i];
#pragma unroll
            for (int j = 0; j < 4; ++j) bb[j] = Bs[k][tx * 4 + j];
#pragma unroll
            for (int i = 0; i < 4; ++i)
#pragma unroll
                for (int j = 0; j < 4; ++j) acc[i][j] += a[i] * bb[j];
        }
        __syncthreads();
    }
#pragma unroll
    for (int i = 0; i < 4; ++i)
#pragma unroll
        for (int j = 0; j < 4; ++j)
            Eb[(size_t)(m0 + ty * 4 + i) * S + n0 + tx * 4 + j] = acc[i][j];
}

__global__ void softmax_kernel(int S) {
    __shared__ float red[128];
    float* row = g_att + (size_t)blockIdx.x * S;
    int t = threadIdx.x;
    float v = row[t];
    red[t] = v;
    __syncthreads();
    for (int off = S >> 1; off > 0; off >>= 1) {
        if (t < off) red[t] = fmaxf(red[t], red[t + off]);
        __syncthreads();
    }
    float m = red[0];
    __syncthreads();
    float e = expf(v - m);
    red[t] = e;
    __syncthreads();
    for (int off = S >> 1; off > 0; off >>= 1) {
        if (t < off) red[t] += red[t + off];
        __syncthreads();
    }
    row[t] = e / red[0];
}

// ---------------------------------------------------------------------------
// Host orchestration
// ---------------------------------------------------------------------------
static void process_map(const float* x, int S, float* out, int brw, int brh,
                        const float* qw, const float* qb, const float* kw, const float* kb,
                        const float* vw, const float* vb, const float* sc,
                        float* qkv, float* xt, float* att, float* wc, float* bc) {
    const size_t SS = (size_t)S * S;
    const bool big = (S == 128);
    dim3 t32(32, 8);

    // X^T (pixel-major [SS][C]) for QKV projection B operand
    transpose_kernel<<<dim3(SS / 32, C_ / 32, B_), t32>>>(x, xt, C_, (int)SS,
                                                          1, C_ * SS, 0, C_ * SS, 0);

    for (int pass = 0; pass < 2; ++pass) {
        int br = pass ? brh : brw;
        build_wc_kernel<<<(MR * C_ + 255) / 256, 256>>>(qw, qb, kw, kb, vw, vb, br);
        // Q,K rows 0..63 in fp32 (precision for logits)
        proj_kernel<<<dim3(SS / 64, 1, B_), 256>>>(x, (int)SS);
        // V rows 64..319 via tensor cores
        mma_gemm<128><<<dim3(SS / 128, 2, B_), 256, 73728>>>(
            wc + 64 * C_, C_, 0, 1,
            xt, C_, C_ * SS,
            qkv + 64 * SS, SS, (size_t)MR * SS,
            C_, 256, 0, bc + 64, nullptr, sc, br);

        if (pass == 0) logits_w_kernel<<<dim3(S / 64, S / 64, B_), 256>>>(S);
        else           logits_h_kernel<<<dim3(S / 64, S / 64, B_), 256>>>(S);
        softmax_kernel<<<B_ * S, S>>>(S);

        if (pass == 0) {
            // apply-W: out = 2x + s * V @ A^T   (A operand rows = V[(c,h)][v])
            if (big)
                mma_gemm<128><<<dim3(1, C_ * S / 128, B_), 256, 73728>>>(
                    qkv + 64 * SS, S, (size_t)MR * SS, 1,
                    att, S, SS,
                    out, S, (size_t)C_ * SS,
                    S, C_ * S, 2, nullptr, x, sc, br);
            else
                mma_gemm<64><<<dim3(1, C_ * S / 128, B_), 256, 55296>>>(
                    qkv + 64 * SS, S, (size_t)MR * SS, 1,
                    att, S, SS,
                    out, S, (size_t)C_ * SS,
                    S, C_ * S, 2, nullptr, x, sc, br);
        } else {
            // spatial transpose of V into xt (Xt no longer needed)
            transpose_kernel<<<dim3(S / 32, S / 32, B_ * C_), t32>>>(
                qkv + 64 * SS, xt, S, S, C_, (size_t)MR * SS, SS, (size_t)C_ * SS, SS);
            // apply-H: out += s * A @ V   (B operand rows = Vt[w][v])
            if (big)
                mma_gemm<128><<<dim3(1, 1, B_ * C_), 256, 73728>>>(
                    att, S, SS, C_,
                    xt, S, SS,
                    out, S, SS,
                    S, S, 3, nullptr, nullptr, sc, br);
            else
                mma_gemm<64><<<dim3(1, 1, B_ * C_), 256, 55296>>>(
                    att, S, SS, C_,
                    xt, S, SS,
                    out, S, SS,
                    S, S, 3, nullptr, nullptr, sc, br);
        }
    }
}

extern "C" void kernel_launch(void* const* d_in, const int* in_sizes, int n_in,
                              void* d_out, int out_size) {
    const float* tmap = (const float*)d_in[0];
    const float* smap = (const float*)d_in[1];
    const float* qw   = (const float*)d_in[2];
    const float* qb   = (const float*)d_in[3];
    const float* kw   = (const float*)d_in[4];
    const float* kb   = (const float*)d_in[5];
    const float* vw   = (const float*)d_in[6];
    const float* vb   = (const float*)d_in[7];
    const float* sc   = (const float*)d_in[8];

    cudaFuncSetAttribute(mma_gemm<128>, cudaFuncAttributeMaxDynamicSharedMemorySize, 73728);
    cudaFuncSetAttribute(mma_gemm<64>,  cudaFuncAttributeMaxDynamicSharedMemorySize, 55296);

    void *p_qkv, *p_xt, *p_att, *p_wc, *p_bc;
    cudaGetSymbolAddress(&p_qkv, g_qkv);
    cudaGetSymbolAddress(&p_xt,  g_xt);
    cudaGetSymbolAddress(&p_att, g_att);
    cudaGetSymbolAddress(&p_wc,  g_wc);
    cudaGetSymbolAddress(&p_bc,  g_bc);

    float* tout = (float*)d_out;
    float* sout = tout + (size_t)B_ * C_ * 64 * 64;

    process_map(tmap, 64,  tout, 0, 2, qw, qb, kw, kb, vw, vb, sc,
                (float*)p_qkv, (float*)p_xt, (float*)p_att, (float*)p_wc, (float*)p_bc);
    process_map(smap, 128, sout, 1, 3, qw, qb, kw, kb, vw, vb, sc,
                (float*)p_qkv, (float*)p_xt, (float*)p_att, (float*)p_wc, (float*)p_bc);
}

// round 12
// speedup vs baseline: 1.6131x; 1.1005x over previous
#include <cuda_runtime.h>
#include <cstdint>

// ===========================================================================
// PAM module on GB300 (base sm_103 target -> mma.sync tf32 tensor cores).
// fp32 SIMT for Q,K projection + logits (precision-critical: logits sd~64,
// near-one-hot softmax -> tf32 rounding there risks argmax flips).
// B=16, C=256, C8=32. Template 64x64, scene 128x128.
// ===========================================================================

#define B_  16
#define C_  256
#define MR  320   // 32 q + 32 k + 256 v

// --------------------------- device scratch --------------------------------
__device__ float g_qkv[(size_t)B_ * MR * 128 * 128];   // 335 MB
__device__ float g_xt [(size_t)B_ * C_ * 128 * 128];   // 268 MB (Xt, later Vt)
__device__ float g_att[(size_t)B_ * 128 * 128];

// --------------------------- PTX helpers -----------------------------------
__device__ __forceinline__ void cp16(void* dst, const void* src) {
    uint32_t d = (uint32_t)__cvta_generic_to_shared(dst);
    asm volatile("cp.async.cg.shared.global [%0], [%1], 16;" :: "r"(d), "l"(src));
}
__device__ __forceinline__ void cp_commit() {
    asm volatile("cp.async.commit_group;" ::: "memory");
}
__device__ __forceinline__ void mma_tf32(float* c, const uint32_t* a, const uint32_t* b) {
    asm volatile("mma.sync.aligned.m16n8k8.row.col.f32.tf32.tf32.f32 "
        "{%0,%1,%2,%3}, {%4,%5,%6,%7}, {%8,%9}, {%0,%1,%2,%3};"
        : "+f"(c[0]), "+f"(c[1]), "+f"(c[2]), "+f"(c[3])
        : "r"(a[0]), "r"(a[1]), "r"(a[2]), "r"(a[3]), "r"(b[0]), "r"(b[1]));
}

// ---------------------------------------------------------------------------
// Batched 32x32 tiled transpose: dst[z][c][r] = src[z][r][c].
// ---------------------------------------------------------------------------
__global__ void transpose_kernel(const float* __restrict__ src, float* __restrict__ dst,
                                 int R, int Cc, int zdiv,
                                 size_t s1, size_t s2, size_t d1, size_t d2) {
    __shared__ float t[32][33];
    int z = blockIdx.z;
    src += (size_t)(z / zdiv) * s1 + (size_t)(z % zdiv) * s2;
    dst += (size_t)(z / zdiv) * d1 + (size_t)(z % zdiv) * d2;
    int x0 = blockIdx.x * 32, y0 = blockIdx.y * 32;
    int tx = threadIdx.x, ty = threadIdx.y;
#pragma unroll
    for (int j = 0; j < 32; j += 8)
        t[ty + j][tx] = src[(size_t)(y0 + ty + j) * Cc + x0 + tx];
    __syncthreads();
#pragma unroll
    for (int j = 0; j < 32; j += 8)
        dst[(size_t)(x0 + ty + j) * R + y0 + tx] = t[tx][ty + j];
}

// ---------------------------------------------------------------------------
// Tensor-core GEMM: D[z][m][n] = sum_k A[m][k] * B[n][k]  (+epilogue)
//   block tile 128 x NT, K tiled by 32; cp.async double buffer; 2 CTAs/SM.
//   mode: 0 = +bias[m]; 2 = out = 2*x + s*d; 3 = out += s*d
// ---------------------------------------------------------------------------
template<int NT>
__global__ __launch_bounds__(256, 2)
void mma_gemm(const float* __restrict__ A, size_t aR, size_t aB, int aZ,
              const float* __restrict__ Bp, size_t bR, size_t bB,
              float* __restrict__ D, size_t dR, size_t dB,
              int K, int Mvalid, int mode,
              const float* __restrict__ bias, const float* __restrict__ xres,
              const float* __restrict__ scal, int br) {
    extern __shared__ float sm[];
    float* Asm[2] = { sm, sm + 128 * 36 };
    float* Bsm[2] = { sm + 2 * 128 * 36, sm + 2 * 128 * 36 + NT * 36 };

    int tid = threadIdx.x, lane = tid & 31, wid = tid >> 5;
    int z = blockIdx.z;
    int m0b = blockIdx.y * 128, n0b = blockIdx.x * NT;

    const float* Ag = A + (size_t)(z / aZ) * aB + (size_t)m0b * aR;
    const float* Bg = Bp + (size_t)z * bB + (size_t)n0b * bR;

    auto fill = [&](int buf, int k0) {
#pragma unroll
        for (int it = 0; it < 4; ++it) {            // A: 128 rows x 32 k
            int i = tid + it * 256;
            int r = i >> 3, c = (i & 7) << 2;
            cp16(&Asm[buf][r * 36 + c], Ag + (size_t)r * aR + k0 + c);
        }
#pragma unroll
        for (int it = 0; it < NT / 32; ++it) {      // B: NT rows x 32 k
            int i = tid + it * 256;
            int r = i >> 3, c = (i & 7) << 2;
            cp16(&Bsm[buf][r * 36 + c], Bg + (size_t)r * bR + k0 + c);
        }
        cp_commit();
    };

    constexpr int WNW = NT / 32;     // warps along n (4 or 2)
    constexpr int MI  = NT / 32;     // m16-tiles per warp (4 or 2)
    int wn = wid % WNW, wm = wid / WNW;
    int wm0 = wm * (MI * 16), wn0 = wn * 32;

    float acc[MI][4][4];
#pragma unroll
    for (int a = 0; a < MI; ++a)
#pragma unroll
        for (int b = 0; b < 4; ++b)
#pragma unroll
            for (int c = 0; c < 4; ++c) acc[a][b][c] = 0.f;

    int nkt = K >> 5;
    fill(0, 0);
    for (int kt = 0; kt < nkt; ++kt) {
        int buf = kt & 1;
        if (kt + 1 < nkt) {
            fill(buf ^ 1, (kt + 1) << 5);
            asm volatile("cp.async.wait_group 1;" ::: "memory");
        } else {
            asm volatile("cp.async.wait_group 0;" ::: "memory");
        }
        __syncthreads();
        const float* At = Asm[buf];
        const float* Bt = Bsm[buf];
#pragma unroll
        for (int ks = 0; ks < 4; ++ks) {
            uint32_t af[MI][4], bf[4][2];
            int kk = ks * 8 + (lane & 3);
#pragma unroll
            for (int mi = 0; mi < MI; ++mi) {
                int m = wm0 + mi * 16 + (lane >> 2);
                af[mi][0] = __float_as_uint(At[m * 36 + kk]);
                af[mi][1] = __float_as_uint(At[(m + 8) * 36 + kk]);
                af[mi][2] = __float_as_uint(At[m * 36 + kk + 4]);
                af[mi][3] = __float_as_uint(At[(m + 8) * 36 + kk + 4]);
            }
#pragma unroll
            for (int ni = 0; ni < 4; ++ni) {
                int n = wn0 + ni * 8 + (lane >> 2);
                bf[ni][0] = __float_as_uint(Bt[n * 36 + kk]);
                bf[ni][1] = __float_as_uint(Bt[n * 36 + kk + 4]);
            }
#pragma unroll
            for (int mi = 0; mi < MI; ++mi)
#pragma unroll
                for (int ni = 0; ni < 4; ++ni)
                    mma_tf32(acc[mi][ni], af[mi], bf[ni]);
        }
        __syncthreads();
    }

    // Epilogue straight from accumulators (coalesced float2 per thread)
    float s = (mode >= 2) ? scal[br] : 0.f;
#pragma unroll
    for (int mi = 0; mi < MI; ++mi)
#pragma unroll
        for (int ni = 0; ni < 4; ++ni)
#pragma unroll
            for (int h = 0; h < 2; ++h) {
                int row = m0b + wm0 + mi * 16 + (lane >> 2) + h * 8;
                int col = n0b + wn0 + ni * 8 + (lane & 3) * 2;
                if (row < Mvalid) {
                    size_t off = (size_t)z * dB + (size_t)row * dR + col;
                    float d0 = acc[mi][ni][h * 2], d1 = acc[mi][ni][h * 2 + 1];
                    float2 v;
                    if (mode == 0) {
                        float bi = bias[row];
                        v = make_float2(d0 + bi, d1 + bi);
                    } else if (mode == 2) {
                        float2 x2 = *(const float2*)(xres + off);
                        v = make_float2(2.f * x2.x + s * d0, 2.f * x2.y + s * d1);
                    } else {
                        float2 o = *(const float2*)(D + off);
                        v = make_float2(o.x + s * d0, o.y + s * d1);
                    }
                    *(float2*)(D + off) = v;
                }
            }
}

// ---------------------------------------------------------------------------
// fp32 SIMT: Q,K projection (rows 0..63) reading qw/kw directly.
// Out[b,m,n] = sum_k W[m,k] * X[b,k,n] + b[m].  grid = (HW/64, 1, B)
// ---------------------------------------------------------------------------
__global__ __launch_bounds__(256)
void proj_kernel(const float* __restrict__ x, int HW,
                 const float* __restrict__ qw, const float* __restrict__ qb,
                 const float* __restrict__ kw, const float* __restrict__ kb, int br) {
    __shared__ float As[16][68];
    __shared__ float Bs[16][68];
    int b  = blockIdx.z;
    int n0 = blockIdx.x * 64;
    const float* Xb = x + (size_t)b * C_ * HW;
    float*       Ob = g_qkv + (size_t)b * MR * HW;
    const float* Qw = qw + (size_t)br * 32 * C_;
    const float* Kw = kw + (size_t)br * 32 * C_;

    int tid = threadIdx.x, tx = tid & 15, ty = tid >> 4;
    float acc[4][4] = {};

    for (int k0 = 0; k0 < C_; k0 += 16) {
#pragma unroll
        for (int i = 0; i < 4; ++i) {
            int idx = tid + i * 256;
            int m = idx >> 4, k = idx & 15;
            As[k][m] = (m < 32) ? Qw[m * C_ + k0 + k] : Kw[(m - 32) * C_ + k0 + k];
        }
#pragma unroll
        for (int i = 0; i < 4; ++i) {
            int idx = tid + i * 256;
            int n = idx & 63, k = idx >> 6;
            Bs[k][n] = Xb[(size_t)(k0 + k) * HW + n0 + n];
        }
        __syncthreads();
#pragma unroll
        for (int k = 0; k < 16; ++k) {
            float a[4], bb[4];
#pragma unroll
            for (int i = 0; i < 4; ++i) a[i]  = As[k][ty * 4 + i];
#pragma unroll
            for (int j = 0; j < 4; ++j) bb[j] = Bs[k][tx * 4 + j];
#pragma unroll
            for (int i = 0; i < 4; ++i)
#pragma unroll
                for (int j = 0; j < 4; ++j) acc[i][j] += a[i] * bb[j];
        }
        __syncthreads();
    }
#pragma unroll
    for (int i = 0; i < 4; ++i) {
        int m = ty * 4 + i;
        float bias = (m < 32) ? qb[br * 32 + m] : kb[br * 32 + m - 32];
#pragma unroll
        for (int j = 0; j < 4; ++j)
            Ob[(size_t)m * HW + n0 + tx * 4 + j] = acc[i][j] + bias;
    }
}

// ---------------------------------------------------------------------------
// fp32 SIMT logits (both maps): over-W and over-H.
// ---------------------------------------------------------------------------
__global__ __launch_bounds__(256)
void logits_w_kernel(int S) {
    __shared__ float As[16][68];
    __shared__ float Bs[16][68];
    int SS = S * S, F = 32 * S;
    const float* Qb = g_qkv + (size_t)blockIdx.z * MR * SS;
    const float* Kb = Qb + (size_t)32 * SS;
    float* Eb = g_att + (size_t)blockIdx.z * SS;
    int m0 = blockIdx.y * 64, n0 = blockIdx.x * 64;
    int tid = threadIdx.x, tx = tid & 15, ty = tid >> 4;
    float acc[4][4] = {};
    for (int k0 = 0; k0 < F; k0 += 16) {
#pragma unroll
        for (int i = 0; i < 4; ++i) {
            int idx = tid + i * 256;
            int n = idx & 63, k = idx >> 6;
            As[k][n] = Qb[(size_t)(k0 + k) * S + m0 + n];
            Bs[k][n] = Kb[(size_t)(k0 + k) * S + n0 + n];
        }
        __syncthreads();
#pragma unroll
        for (int k = 0; k < 16; ++k) {
            float a[4], bb[4];
#pragma unroll
            for (int i = 0; i < 4; ++i) a[i] = As[k][ty * 4 + i];
#pragma unroll
            for (int j = 0; j < 4; ++j) bb[j] = Bs[k][tx * 4 + j];
#pragma unroll
            for (int i = 0; i < 4; ++i)
#pragma unroll
                for (int j = 0; j < 4; ++j) acc[i][j] += a[i] * bb[j];
        }
        __syncthreads();
    }
#pragma unroll
    for (int i = 0; i < 4; ++i)
#pragma unroll
        for (int j = 0; j < 4; ++j)
            Eb[(size_t)(m0 + ty * 4 + i) * S + n0 + tx * 4 + j] = acc[i][j];
}

__global__ __launch_bounds__(256)
void logits_h_kernel(int S) {
    __shared__ float As[16][68];
    __shared__ float Bs[16][68];
    int SS = S * S, F = 32 * S;
    const float* Qb = g_qkv + (size_t)blockIdx.z * MR * SS;
    const float* Kb = Qb + (size_t)32 * SS;
    float* Eb = g_att + (size_t)blockIdx.z * SS;
    int m0 = blockIdx.y * 64, n0 = blockIdx.x * 64;
    int tid = threadIdx.x, tx = tid & 15, ty = tid >> 4;
    float acc[4][4] = {};
    for (int k0 = 0; k0 < F; k0 += 16) {
        int o = k0 / S, w0 = k0 % S;
        const float* Qo = Qb + (size_t)o * SS;
        const float* Ko = Kb + (size_t)o * SS;
#pragma unroll
        for (int i = 0; i < 4; ++i) {
            int idx = tid + i * 256;
            int k = idx & 15, m = idx >> 4;
            As[k][m] = Qo[(size_t)(m0 + m) * S + w0 + k];
            Bs[k][m] = Ko[(size_t)(n0 + m) * S + w0 + k];
        }
        __syncthreads();
#pragma unroll
        for (int k = 0; k < 16; ++k) {
            float a[4], bb[4];
#pragma unroll
            for (int i = 0; i < 4; ++i) a[i] = As[k][ty * 4 + i];
#pragma unroll
            for (int j = 0; j < 4; ++j) bb[j] = Bs[k][tx * 4 + j];
#pragma unroll
            for (int i = 0; i < 4; ++i)
#pragma unroll
                for (int j = 0; j < 4; ++j) acc[i][j] += a[i] * bb[j];
        }
        __syncthreads();
    }
#pragma unroll
    for (int i = 0; i < 4; ++i)
#pragma unroll
        for (int j = 0; j < 4; ++j)
            Eb[(size_t)(m0 + ty * 4 + i) * S + n0 + tx * 4 + j] = acc[i][j];
}

__global__ void softmax_kernel(int S) {
    __shared__ float red[128];
    float* row = g_att + (size_t)blockIdx.x * S;
    int t = threadIdx.x;
    float v = row[t];
    red[t] = v;
    __syncthreads();
    for (int off = S >> 1; off > 0; off >>= 1) {
        if (t < off) red[t] = fmaxf(red[t], red[t + off]);
        __syncthreads();
    }
    float m = red[0];
    __syncthreads();
    float e = expf(v - m);
    red[t] = e;
    __syncthreads();
    for (int off = S >> 1; off > 0; off >>= 1) {
        if (t < off) red[t] += red[t + off];
        __syncthreads();
    }
    row[t] = e / red[0];
}

// ---------------------------------------------------------------------------
// Host orchestration
// ---------------------------------------------------------------------------
static void process_map(const float* x, int S, float* out, int brw, int brh,
                        const float* qw, const float* qb, const float* kw, const float* kb,
                        const float* vw, const float* vb, const float* sc,
                        float* qkv, float* xt, float* att) {
    const size_t SS = (size_t)S * S;
    const bool big = (S == 128);
    dim3 t32(32, 8);

    // X^T (pixel-major [SS][C]) for QKV projection B operand
    transpose_kernel<<<dim3(SS / 32, C_ / 32, B_), t32>>>(x, xt, C_, (int)SS,
                                                          1, C_ * SS, 0, C_ * SS, 0);

    for (int pass = 0; pass < 2; ++pass) {
        int br = pass ? brh : brw;
        // Q,K rows 0..63 in fp32 (precision for logits)
        proj_kernel<<<dim3(SS / 64, 1, B_), 256>>>(x, (int)SS, qw, qb, kw, kb, br);
        // V rows 64..319 via tensor cores, A = vw[br] directly
        mma_gemm<128><<<dim3(SS / 128, 2, B_), 256, 73728>>>(
            vw + (size_t)br * C_ * C_, C_, 0, 1,
            xt, C_, C_ * SS,
            qkv + 64 * SS, SS, (size_t)MR * SS,
            C_, 256, 0, vb + (size_t)br * C_, nullptr, sc, br);

        if (pass == 0) logits_w_kernel<<<dim3(S / 64, S / 64, B_), 256>>>(S);
        else           logits_h_kernel<<<dim3(S / 64, S / 64, B_), 256>>>(S);
        softmax_kernel<<<B_ * S, S>>>(S);

        if (pass == 0) {
            // apply-W: out = 2x + s * V @ A^T
            if (big)
                mma_gemm<128><<<dim3(1, C_ * S / 128, B_), 256, 73728>>>(
                    qkv + 64 * SS, S, (size_t)MR * SS, 1,
                    att, S, SS,
                    out, S, (size_t)C_ * SS,
                    S, C_ * S, 2, nullptr, x, sc, br);
            else
                mma_gemm<64><<<dim3(1, C_ * S / 128, B_), 256, 55296>>>(
                    qkv + 64 * SS, S, (size_t)MR * SS, 1,
                    att, S, SS,
                    out, S, (size_t)C_ * SS,
                    S, C_ * S, 2, nullptr, x, sc, br);
        } else {
            // spatial transpose of V into xt (Xt no longer needed)
            transpose_kernel<<<dim3(S / 32, S / 32, B_ * C_), t32>>>(
                qkv + 64 * SS, xt, S, S, C_, (size_t)MR * SS, SS, (size_t)C_ * SS, SS);
            // apply-H: out += s * A @ V
            if (big)
                mma_gemm<128><<<dim3(1, 1, B_ * C_), 256, 73728>>>(
                    att, S, SS, C_,
                    xt, S, SS,
                    out, S, SS,
                    S, S, 3, nullptr, nullptr, sc, br);
            else
                mma_gemm<64><<<dim3(1, 1, B_ * C_), 256, 55296>>>(
                    att, S, SS, C_,
                    xt, S, SS,
                    out, S, SS,
                    S, S, 3, nullptr, nullptr, sc, br);
        }
    }
}

extern "C" void kernel_launch(void* const* d_in, const int* in_sizes, int n_in,
                              void* d_out, int out_size) {
    const float* tmap = (const float*)d_in[0];
    const float* smap = (const float*)d_in[1];
    const float* qw   = (const float*)d_in[2];
    const float* qb   = (const float*)d_in[3];
    const float* kw   = (const float*)d_in[4];
    const float* kb   = (const float*)d_in[5];
    const float* vw   = (const float*)d_in[6];
    const float* vb   = (const float*)d_in[7];
    const float* sc   = (const float*)d_in[8];

    cudaFuncSetAttribute(mma_gemm<128>, cudaFuncAttributeMaxDynamicSharedMemorySize, 73728);
    cudaFuncSetAttribute(mma_gemm<64>,  cudaFuncAttributeMaxDynamicSharedMemorySize, 55296);

    void *p_qkv, *p_xt, *p_att;
    cudaGetSymbolAddress(&p_qkv, g_qkv);
    cudaGetSymbolAddress(&p_xt,  g_xt);
    cudaGetSymbolAddress(&p_att, g_att);

    float* tout = (float*)d_out;
    float* sout = tout + (size_t)B_ * C_ * 64 * 64;

    process_map(tmap, 64,  tout, 0, 2, qw, qb, kw, kb, vw, vb, sc,
                (float*)p_qkv, (float*)p_xt, (float*)p_att);
    process_map(smap, 128, sout, 1, 3, qw, qb, kw, kb, vw, vb, sc,
                (float*)p_qkv, (float*)p_xt, (float*)p_att);
}

// round 13
// speedup vs baseline: 2.2004x; 1.3641x over previous
#include <cuda_runtime.h>
#include <cstdint>

// ===========================================================================
// PAM module on GB300 (base sm_103 target -> mma.sync tf32 tensor cores).
// fp32 SIMT for Q,K projection + split-K logits (precision-critical path);
// tf32 mma.sync for V-proj / apply-W / apply-H.
// B=16, C=256, C8=32. Template 64x64, scene 128x128.
// ===========================================================================

#define B_  16
#define C_  256
#define MR  320   // 32 q + 32 k + 256 v

// --------------------------- device scratch --------------------------------
__device__ float g_qkv [(size_t)B_ * MR * 128 * 128];   // 335 MB
__device__ float g_xt  [(size_t)B_ * C_ * 128 * 128];   // 268 MB (Xt, later Vt)
__device__ float g_att [(size_t)B_ * 128 * 128];
__device__ float g_part[(size_t)16 * B_ * 128 * 128];   // split-K logits partials

// --------------------------- PTX helpers -----------------------------------
__device__ __forceinline__ void cp16(void* dst, const void* src) {
    uint32_t d = (uint32_t)__cvta_generic_to_shared(dst);
    asm volatile("cp.async.cg.shared.global [%0], [%1], 16;" :: "r"(d), "l"(src));
}
__device__ __forceinline__ void cp_commit() {
    asm volatile("cp.async.commit_group;" ::: "memory");
}
__device__ __forceinline__ void mma_tf32(float* c, const uint32_t* a, const uint32_t* b) {
    asm volatile("mma.sync.aligned.m16n8k8.row.col.f32.tf32.tf32.f32 "
        "{%0,%1,%2,%3}, {%4,%5,%6,%7}, {%8,%9}, {%0,%1,%2,%3};"
        : "+f"(c[0]), "+f"(c[1]), "+f"(c[2]), "+f"(c[3])
        : "r"(a[0]), "r"(a[1]), "r"(a[2]), "r"(a[3]), "r"(b[0]), "r"(b[1]));
}

// ---------------------------------------------------------------------------
// Batched 32x32 tiled transpose: dst[z][c][r] = src[z][r][c].
// ---------------------------------------------------------------------------
__global__ void transpose_kernel(const float* __restrict__ src, float* __restrict__ dst,
                                 int R, int Cc, int zdiv,
                                 size_t s1, size_t s2, size_t d1, size_t d2) {
    __shared__ float t[32][33];
    int z = blockIdx.z;
    src += (size_t)(z / zdiv) * s1 + (size_t)(z % zdiv) * s2;
    dst += (size_t)(z / zdiv) * d1 + (size_t)(z % zdiv) * d2;
    int x0 = blockIdx.x * 32, y0 = blockIdx.y * 32;
    int tx = threadIdx.x, ty = threadIdx.y;
#pragma unroll
    for (int j = 0; j < 32; j += 8)
        t[ty + j][tx] = src[(size_t)(y0 + ty + j) * Cc + x0 + tx];
    __syncthreads();
#pragma unroll
    for (int j = 0; j < 32; j += 8)
        dst[(size_t)(x0 + ty + j) * R + y0 + tx] = t[tx][ty + j];
}

// ---------------------------------------------------------------------------
// Tensor-core GEMM: D[z][m][n] = sum_k A[m][k] * B[n][k]  (+epilogue)
//   block tile 128 x NT, K tiled by 32; cp.async double buffer; 2 CTAs/SM.
//   mode: 0 = +bias[m]; 2 = out = 2*x + s*d; 3 = out += s*d
// ---------------------------------------------------------------------------
template<int NT>
__global__ __launch_bounds__(256, 2)
void mma_gemm(const float* __restrict__ A, size_t aR, size_t aB, int aZ,
              const float* __restrict__ Bp, size_t bR, size_t bB,
              float* __restrict__ D, size_t dR, size_t dB,
              int K, int Mvalid, int mode,
              const float* __restrict__ bias, const float* __restrict__ xres,
              const float* __restrict__ scal, int br) {
    extern __shared__ float sm[];
    float* Asm[2] = { sm, sm + 128 * 36 };
    float* Bsm[2] = { sm + 2 * 128 * 36, sm + 2 * 128 * 36 + NT * 36 };

    int tid = threadIdx.x, lane = tid & 31, wid = tid >> 5;
    int z = blockIdx.z;
    int m0b = blockIdx.y * 128, n0b = blockIdx.x * NT;

    const float* Ag = A + (size_t)(z / aZ) * aB + (size_t)m0b * aR;
    const float* Bg = Bp + (size_t)z * bB + (size_t)n0b * bR;

    auto fill = [&](int buf, int k0) {
#pragma unroll
        for (int it = 0; it < 4; ++it) {            // A: 128 rows x 32 k
            int i = tid + it * 256;
            int r = i >> 3, c = (i & 7) << 2;
            cp16(&Asm[buf][r * 36 + c], Ag + (size_t)r * aR + k0 + c);
        }
#pragma unroll
        for (int it = 0; it < NT / 32; ++it) {      // B: NT rows x 32 k
            int i = tid + it * 256;
            int r = i >> 3, c = (i & 7) << 2;
            cp16(&Bsm[buf][r * 36 + c], Bg + (size_t)r * bR + k0 + c);
        }
        cp_commit();
    };

    constexpr int WNW = NT / 32;     // warps along n (4 or 2)
    constexpr int MI  = NT / 32;     // m16-tiles per warp (4 or 2)
    int wn = wid % WNW, wm = wid / WNW;
    int wm0 = wm * (MI * 16), wn0 = wn * 32;

    float acc[MI][4][4];
#pragma unroll
    for (int a = 0; a < MI; ++a)
#pragma unroll
        for (int b = 0; b < 4; ++b)
#pragma unroll
            for (int c = 0; c < 4; ++c) acc[a][b][c] = 0.f;

    int nkt = K >> 5;
    fill(0, 0);
    for (int kt = 0; kt < nkt; ++kt) {
        int buf = kt & 1;
        if (kt + 1 < nkt) {
            fill(buf ^ 1, (kt + 1) << 5);
            asm volatile("cp.async.wait_group 1;" ::: "memory");
        } else {
            asm volatile("cp.async.wait_group 0;" ::: "memory");
        }
        __syncthreads();
        const float* At = Asm[buf];
        const float* Bt = Bsm[buf];
#pragma unroll
        for (int ks = 0; ks < 4; ++ks) {
            uint32_t af[MI][4], bf[4][2];
            int kk = ks * 8 + (lane & 3);
#pragma unroll
            for (int mi = 0; mi < MI; ++mi) {
                int m = wm0 + mi * 16 + (lane >> 2);
                af[mi][0] = __float_as_uint(At[m * 36 + kk]);
                af[mi][1] = __float_as_uint(At[(m + 8) * 36 + kk]);
                af[mi][2] = __float_as_uint(At[m * 36 + kk + 4]);
                af[mi][3] = __float_as_uint(At[(m + 8) * 36 + kk + 4]);
            }
#pragma unroll
            for (int ni = 0; ni < 4; ++ni) {
                int n = wn0 + ni * 8 + (lane >> 2);
                bf[ni][0] = __float_as_uint(Bt[n * 36 + kk]);
                bf[ni][1] = __float_as_uint(Bt[n * 36 + kk + 4]);
            }
#pragma unroll
            for (int mi = 0; mi < MI; ++mi)
#pragma unroll
                for (int ni = 0; ni < 4; ++ni)
                    mma_tf32(acc[mi][ni], af[mi], bf[ni]);
        }
        __syncthreads();
    }

    // Epilogue straight from accumulators (coalesced float2 per thread)
    float s = (mode >= 2) ? scal[br] : 0.f;
#pragma unroll
    for (int mi = 0; mi < MI; ++mi)
#pragma unroll
        for (int ni = 0; ni < 4; ++ni)
#pragma unroll
            for (int h = 0; h < 2; ++h) {
                int row = m0b + wm0 + mi * 16 + (lane >> 2) + h * 8;
                int col = n0b + wn0 + ni * 8 + (lane & 3) * 2;
                if (row < Mvalid) {
                    size_t off = (size_t)z * dB + (size_t)row * dR + col;
                    float d0 = acc[mi][ni][h * 2], d1 = acc[mi][ni][h * 2 + 1];
                    float2 v;
                    if (mode == 0) {
                        float bi = bias[row];
                        v = make_float2(d0 + bi, d1 + bi);
                    } else if (mode == 2) {
                        float2 x2 = *(const float2*)(xres + off);
                        v = make_float2(2.f * x2.x + s * d0, 2.f * x2.y + s * d1);
                    } else {
                        float2 o = *(const float2*)(D + off);
                        v = make_float2(o.x + s * d0, o.y + s * d1);
                    }
                    *(float2*)(D + off) = v;
                }
            }
}

// ---------------------------------------------------------------------------
// fp32 SIMT: Q,K projection (rows 0..63) reading qw/kw directly.
// ---------------------------------------------------------------------------
__global__ __launch_bounds__(256)
void proj_kernel(const float* __restrict__ x, int HW,
                 const float* __restrict__ qw, const float* __restrict__ qb,
                 const float* __restrict__ kw, const float* __restrict__ kb, int br) {
    __shared__ float As[16][68];
    __shared__ float Bs[16][68];
    int b  = blockIdx.z;
    int n0 = blockIdx.x * 64;
    const float* Xb = x + (size_t)b * C_ * HW;
    float*       Ob = g_qkv + (size_t)b * MR * HW;
    const float* Qw = qw + (size_t)br * 32 * C_;
    const float* Kw = kw + (size_t)br * 32 * C_;

    int tid = threadIdx.x, tx = tid & 15, ty = tid >> 4;
    float acc[4][4] = {};

    for (int k0 = 0; k0 < C_; k0 += 16) {
#pragma unroll
        for (int i = 0; i < 4; ++i) {
            int idx = tid + i * 256;
            int m = idx >> 4, k = idx & 15;
            As[k][m] = (m < 32) ? Qw[m * C_ + k0 + k] : Kw[(m - 32) * C_ + k0 + k];
        }
#pragma unroll
        for (int i = 0; i < 4; ++i) {
            int idx = tid + i * 256;
            int n = idx & 63, k = idx >> 6;
            Bs[k][n] = Xb[(size_t)(k0 + k) * HW + n0 + n];
        }
        __syncthreads();
#pragma unroll
        for (int k = 0; k < 16; ++k) {
            float a[4], bb[4];
#pragma unroll
            for (int i = 0; i < 4; ++i) a[i]  = As[k][ty * 4 + i];
#pragma unroll
            for (int j = 0; j < 4; ++j) bb[j] = Bs[k][tx * 4 + j];
#pragma unroll
            for (int i = 0; i < 4; ++i)
#pragma unroll
                for (int j = 0; j < 4; ++j) acc[i][j] += a[i] * bb[j];
        }
        __syncthreads();
    }
#pragma unroll
    for (int i = 0; i < 4; ++i) {
        int m = ty * 4 + i;
        float bias = (m < 32) ? qb[br * 32 + m] : kb[br * 32 + m - 32];
#pragma unroll
        for (int j = 0; j < 4; ++j)
            Ob[(size_t)m * HW + n0 + tx * 4 + j] = acc[i][j] + bias;
    }
}

// ---------------------------------------------------------------------------
// Split-K fp32 logits. z = b*CH + ch; chunk = F/CH k-values (multiple of S).
// Partials -> g_part[z][S][S].
// ---------------------------------------------------------------------------
__global__ __launch_bounds__(256)
void logits_w_kernel(int S, int CH) {
    __shared__ float As[16][68];
    __shared__ float Bs[16][68];
    int SS = S * S, F = 32 * S;
    int b = blockIdx.z / CH, ch = blockIdx.z % CH;
    int kbeg = ch * (F / CH), kend = kbeg + F / CH;
    const float* Qb = g_qkv + (size_t)b * MR * SS;
    const float* Kb = Qb + (size_t)32 * SS;
    float* Eb = g_part + (size_t)blockIdx.z * SS;
    int m0 = blockIdx.y * 64, n0 = blockIdx.x * 64;
    int tid = threadIdx.x, tx = tid & 15, ty = tid >> 4;
    float acc[4][4] = {};
    for (int k0 = kbeg; k0 < kend; k0 += 16) {
#pragma unroll
        for (int i = 0; i < 4; ++i) {
            int idx = tid + i * 256;
            int n = idx & 63, k = idx >> 6;
            As[k][n] = Qb[(size_t)(k0 + k) * S + m0 + n];
            Bs[k][n] = Kb[(size_t)(k0 + k) * S + n0 + n];
        }
        __syncthreads();
#pragma unroll
        for (int k = 0; k < 16; ++k) {
            float a[4], bb[4];
#pragma unroll
            for (int i = 0; i < 4; ++i) a[i] = As[k][ty * 4 + i];
#pragma unroll
            for (int j = 0; j < 4; ++j) bb[j] = Bs[k][tx * 4 + j];
#pragma unroll
            for (int i = 0; i < 4; ++i)
#pragma unroll
                for (int j = 0; j < 4; ++j) acc[i][j] += a[i] * bb[j];
        }
        __syncthreads();
    }
#pragma unroll
    for (int i = 0; i < 4; ++i)
#pragma unroll
        for (int j = 0; j < 4; ++j)
            Eb[(size_t)(m0 + ty * 4 + i) * S + n0 + tx * 4 + j] = acc[i][j];
}

__global__ __launch_bounds__(256)
void logits_h_kernel(int S, int CH) {
    __shared__ float As[16][68];
    __shared__ float Bs[16][68];
    int SS = S * S, F = 32 * S;
    int b = blockIdx.z / CH, ch = blockIdx.z % CH;
    int kbeg = ch * (F / CH), kend = kbeg + F / CH;
    const float* Qb = g_qkv + (size_t)b * MR * SS;
    const float* Kb = Qb + (size_t)32 * SS;
    float* Eb = g_part + (size_t)blockIdx.z * SS;
    int m0 = blockIdx.y * 64, n0 = blockIdx.x * 64;
    int tid = threadIdx.x, tx = tid & 15, ty = tid >> 4;
    float acc[4][4] = {};
    for (int k0 = kbeg; k0 < kend; k0 += 16) {
        int o = k0 / S, w0 = k0 % S;
        const float* Qo = Qb + (size_t)o * SS;
        const float* Ko = Kb + (size_t)o * SS;
#pragma unroll
        for (int i = 0; i < 4; ++i) {
            int idx = tid + i * 256;
            int k = idx & 15, m = idx >> 4;
            As[k][m] = Qo[(size_t)(m0 + m) * S + w0 + k];
            Bs[k][m] = Ko[(size_t)(n0 + m) * S + w0 + k];
        }
        __syncthreads();
#pragma unroll
        for (int k = 0; k < 16; ++k) {
            float a[4], bb[4];
#pragma unroll
            for (int i = 0; i < 4; ++i) a[i] = As[k][ty * 4 + i];
#pragma unroll
            for (int j = 0; j < 4; ++j) bb[j] = Bs[k][tx * 4 + j];
#pragma unroll
            for (int i = 0; i < 4; ++i)
#pragma unroll
                for (int j = 0; j < 4; ++j) acc[i][j] += a[i] * bb[j];
        }
        __syncthreads();
    }
#pragma unroll
    for (int i = 0; i < 4; ++i)
#pragma unroll
        for (int j = 0; j < 4; ++j)
            Eb[(size_t)(m0 + ty * 4 + i) * S + n0 + tx * 4 + j] = acc[i][j];
}

// ---------------------------------------------------------------------------
// Fused split-K reduce + row softmax: att[b,h,:] = softmax(sum_ch part).
// grid = B*S rows, blockDim = S. Fixed summation order -> deterministic.
// ---------------------------------------------------------------------------
__global__ void reduce_softmax_kernel(int S, int CH) {
    __shared__ float red[128];
    int SS = S * S;
    int b = blockIdx.x / S, h = blockIdx.x % S;
    int t = threadIdx.x;
    const float* base = g_part + (size_t)b * CH * SS + (size_t)h * S + t;
    float v = 0.f;
    for (int ch = 0; ch < CH; ++ch) v += base[(size_t)ch * SS];
    red[t] = v;
    __syncthreads();
    for (int off = S >> 1; off > 0; off >>= 1) {
        if (t < off) red[t] = fmaxf(red[t], red[t + off]);
        __syncthreads();
    }
    float m = red[0];
    __syncthreads();
    float e = expf(v - m);
    red[t] = e;
    __syncthreads();
    for (int off = S >> 1; off > 0; off >>= 1) {
        if (t < off) red[t] += red[t + off];
        __syncthreads();
    }
    g_att[(size_t)b * SS + (size_t)h * S + t] = e / red[0];
}

// ---------------------------------------------------------------------------
// Host orchestration
// ---------------------------------------------------------------------------
static void process_map(const float* x, int S, float* out, int brw, int brh,
                        const float* qw, const float* qb, const float* kw, const float* kb,
                        const float* vw, const float* vb, const float* sc,
                        float* qkv, float* xt, float* att) {
    const size_t SS = (size_t)S * S;
    const bool big = (S == 128);
    const int CH = big ? 8 : 16;         // split-K chunks (chunk = mult. of S)
    dim3 t32(32, 8);

    // X^T (pixel-major [SS][C]) for QKV projection B operand
    transpose_kernel<<<dim3(SS / 32, C_ / 32, B_), t32>>>(x, xt, C_, (int)SS,
                                                          1, C_ * SS, 0, C_ * SS, 0);

    for (int pass = 0; pass < 2; ++pass) {
        int br = pass ? brh : brw;
        // Q,K rows 0..63 in fp32 (precision for logits)
        proj_kernel<<<dim3(SS / 64, 1, B_), 256>>>(x, (int)SS, qw, qb, kw, kb, br);
        // V rows 64..319 via tensor cores, A = vw[br] directly
        mma_gemm<128><<<dim3(SS / 128, 2, B_), 256, 73728>>>(
            vw + (size_t)br * C_ * C_, C_, 0, 1,
            xt, C_, C_ * SS,
            qkv + 64 * SS, SS, (size_t)MR * SS,
            C_, 256, 0, vb + (size_t)br * C_, nullptr, sc, br);

        if (pass == 0)
            logits_w_kernel<<<dim3(S / 64, S / 64, B_ * CH), 256>>>(S, CH);
        else
            logits_h_kernel<<<dim3(S / 64, S / 64, B_ * CH), 256>>>(S, CH);
        reduce_softmax_kernel<<<B_ * S, S>>>(S, CH);

        if (pass == 0) {
            // apply-W: out = 2x + s * V @ A^T
            if (big)
                mma_gemm<128><<<dim3(1, C_ * S / 128, B_), 256, 73728>>>(
                    qkv + 64 * SS, S, (size_t)MR * SS, 1,
                    att, S, SS,
                    out, S, (size_t)C_ * SS,
                    S, C_ * S, 2, nullptr, x, sc, br);
            else
                mma_gemm<64><<<dim3(1, C_ * S / 128, B_), 256, 55296>>>(
                    qkv + 64 * SS, S, (size_t)MR * SS, 1,
                    att, S, SS,
                    out, S, (size_t)C_ * SS,
                    S, C_ * S, 2, nullptr, x, sc, br);
        } else {
            // spatial transpose of V into xt (Xt no longer needed)
            transpose_kernel<<<dim3(S / 32, S / 32, B_ * C_), t32>>>(
                qkv + 64 * SS, xt, S, S, C_, (size_t)MR * SS, SS, (size_t)C_ * SS, SS);
            // apply-H: out += s * A @ V
            if (big)
                mma_gemm<128><<<dim3(1, 1, B_ * C_), 256, 73728>>>(
                    att, S, SS, C_,
                    xt, S, SS,
                    out, S, SS,
                    S, S, 3, nullptr, nullptr, sc, br);
            else
                mma_gemm<64><<<dim3(1, 1, B_ * C_), 256, 55296>>>(
                    att, S, SS, C_,
                    xt, S, SS,
                    out, S, SS,
                    S, S, 3, nullptr, nullptr, sc, br);
        }
    }
}

extern "C" void kernel_launch(void* const* d_in, const int* in_sizes, int n_in,
                              void* d_out, int out_size) {
    const float* tmap = (const float*)d_in[0];
    const float* smap = (const float*)d_in[1];
    const float* qw   = (const float*)d_in[2];
    const float* qb   = (const float*)d_in[3];
    const float* kw   = (const float*)d_in[4];
    const float* kb   = (const float*)d_in[5];
    const float* vw   = (const float*)d_in[6];
    const float* vb   = (const float*)d_in[7];
    const float* sc   = (const float*)d_in[8];

    cudaFuncSetAttribute(mma_gemm<128>, cudaFuncAttributeMaxDynamicSharedMemorySize, 73728);
    cudaFuncSetAttribute(mma_gemm<64>,  cudaFuncAttributeMaxDynamicSharedMemorySize, 55296);

    void *p_qkv, *p_xt, *p_att;
    cudaGetSymbolAddress(&p_qkv, g_qkv);
    cudaGetSymbolAddress(&p_xt,  g_xt);
    cudaGetSymbolAddress(&p_att, g_att);

    float* tout = (float*)d_out;
    float* sout = tout + (size_t)B_ * C_ * 64 * 64;

    process_map(tmap, 64,  tout, 0, 2, qw, qb, kw, kb, vw, vb, sc,
                (float*)p_qkv, (float*)p_xt, (float*)p_att);
    process_map(smap, 128, sout, 1, 3, qw, qb, kw, kb, vw, vb, sc,
                (float*)p_qkv, (float*)p_xt, (float*)p_att);
}

// round 14
// speedup vs baseline: 2.5241x; 1.1471x over previous
#include <cuda_runtime.h>
#include <cstdint>

// ===========================================================================
// PAM module on GB300 (base sm_103 target -> mma.sync tf32 tensor cores).
// 3xTF32 (hi/lo split) mma for Q,K projection + logits (precision-critical),
// plain tf32 mma for V-proj / apply-W / apply-H. No SIMT GEMMs left.
// B=16, C=256, C8=32. Template 64x64, scene 128x128.
// ===========================================================================

#define B_  16
#define C_  256
#define MR  320   // 32 q + 32 k + 256 v (V stored at rows 64.. of this stride)

// --------------------------- device scratch --------------------------------
__device__ float g_qkv [(size_t)B_ * MR * 128 * 128];    // V storage (rows 64..319)
__device__ float g_qk  [(size_t)B_ * 128 * 128 * 128];   // Qw,Kw,Qh,Kh (32 rows each)
__device__ float g_xt  [(size_t)B_ * C_ * 128 * 128];    // Xt, later Vt
__device__ float g_att [(size_t)B_ * 128 * 128];
__device__ float g_part[(size_t)32 * B_ * 128 * 128];    // split-K logits partials
__device__ float g_qt  [(size_t)B_ * 128 * 4096];        // Q^T for logits-W
__device__ float g_kt  [(size_t)B_ * 128 * 4096];        // K^T for logits-W
__device__ float g_wqk [128 * C_];                       // stacked QK weights
__device__ float g_bqk [128];                            // stacked QK bias

// --------------------------- PTX helpers -----------------------------------
__device__ __forceinline__ void cp16(void* dst, const void* src) {
    uint32_t d = (uint32_t)__cvta_generic_to_shared(dst);
    asm volatile("cp.async.cg.shared.global [%0], [%1], 16;" :: "r"(d), "l"(src));
}
__device__ __forceinline__ void cp_commit() {
    asm volatile("cp.async.commit_group;" ::: "memory");
}
__device__ __forceinline__ void mma_tf32(float* c, const uint32_t* a, const uint32_t* b) {
    asm volatile("mma.sync.aligned.m16n8k8.row.col.f32.tf32.tf32.f32 "
        "{%0,%1,%2,%3}, {%4,%5,%6,%7}, {%8,%9}, {%0,%1,%2,%3};"
        : "+f"(c[0]), "+f"(c[1]), "+f"(c[2]), "+f"(c[3])
        : "r"(a[0]), "r"(a[1]), "r"(a[2]), "r"(a[3]), "r"(b[0]), "r"(b[1]));
}
__device__ __forceinline__ float to_tf32(float x) {
    float y; asm("cvt.rna.tf32.f32 %0, %1;" : "=f"(y) : "f"(x)); return y;
}

// ---------------------------------------------------------------------------
// Batched 32x32 tiled transpose: dst[z][c][r] = src[z][r][c].
// ---------------------------------------------------------------------------
__global__ void transpose_kernel(const float* __restrict__ src, float* __restrict__ dst,
                                 int R, int Cc, int zdiv,
                                 size_t s1, size_t s2, size_t d1, size_t d2) {
    __shared__ float t[32][33];
    int z = blockIdx.z;
    src += (size_t)(z / zdiv) * s1 + (size_t)(z % zdiv) * s2;
    dst += (size_t)(z / zdiv) * d1 + (size_t)(z % zdiv) * d2;
    int x0 = blockIdx.x * 32, y0 = blockIdx.y * 32;
    int tx = threadIdx.x, ty = threadIdx.y;
#pragma unroll
    for (int j = 0; j < 32; j += 8)
        t[ty + j][tx] = src[(size_t)(y0 + ty + j) * Cc + x0 + tx];
    __syncthreads();
#pragma unroll
    for (int j = 0; j < 32; j += 8)
        dst[(size_t)(x0 + ty + j) * R + y0 + tx] = t[tx][ty + j];
}

// ---------------------------------------------------------------------------
// Plain tf32 tensor GEMM (V-proj / apply-W / apply-H):
//   D[z][m][n] = sum_k A[m][k]*B[n][k]; 128xNT tile; cp.async dbl buffer.
//   mode: 0 = +bias[m]; 2 = out = 2*x + s*d; 3 = out += s*d
// ---------------------------------------------------------------------------
template<int NT>
__global__ __launch_bounds__(256, 2)
void mma_gemm(const float* __restrict__ A, size_t aR, size_t aB, int aZ,
              const float* __restrict__ Bp, size_t bR, size_t bB,
              float* __restrict__ D, size_t dR, size_t dB,
              int K, int Mvalid, int mode,
              const float* __restrict__ bias, const float* __restrict__ xres,
              const float* __restrict__ scal, int br) {
    extern __shared__ float sm[];
    float* Asm[2] = { sm, sm + 128 * 36 };
    float* Bsm[2] = { sm + 2 * 128 * 36, sm + 2 * 128 * 36 + NT * 36 };

    int tid = threadIdx.x, lane = tid & 31, wid = tid >> 5;
    int z = blockIdx.z;
    int m0b = blockIdx.y * 128, n0b = blockIdx.x * NT;

    const float* Ag = A + (size_t)(z / aZ) * aB + (size_t)m0b * aR;
    const float* Bg = Bp + (size_t)z * bB + (size_t)n0b * bR;

    auto fill = [&](int buf, int k0) {
#pragma unroll
        for (int it = 0; it < 4; ++it) {
            int i = tid + it * 256;
            int r = i >> 3, c = (i & 7) << 2;
            cp16(&Asm[buf][r * 36 + c], Ag + (size_t)r * aR + k0 + c);
        }
#pragma unroll
        for (int it = 0; it < NT / 32; ++it) {
            int i = tid + it * 256;
            int r = i >> 3, c = (i & 7) << 2;
            cp16(&Bsm[buf][r * 36 + c], Bg + (size_t)r * bR + k0 + c);
        }
        cp_commit();
    };

    constexpr int WNW = NT / 32;
    constexpr int MI  = NT / 32;
    int wn = wid % WNW, wm = wid / WNW;
    int wm0 = wm * (MI * 16), wn0 = wn * 32;

    float acc[MI][4][4];
#pragma unroll
    for (int a = 0; a < MI; ++a)
#pragma unroll
        for (int b = 0; b < 4; ++b)
#pragma unroll
            for (int c = 0; c < 4; ++c) acc[a][b][c] = 0.f;

    int nkt = K >> 5;
    fill(0, 0);
    for (int kt = 0; kt < nkt; ++kt) {
        int buf = kt & 1;
        if (kt + 1 < nkt) {
            fill(buf ^ 1, (kt + 1) << 5);
            asm volatile("cp.async.wait_group 1;" ::: "memory");
        } else {
            asm volatile("cp.async.wait_group 0;" ::: "memory");
        }
        __syncthreads();
        const float* At = Asm[buf];
        const float* Bt = Bsm[buf];
#pragma unroll
        for (int ks = 0; ks < 4; ++ks) {
            uint32_t af[MI][4], bf[4][2];
            int kk = ks * 8 + (lane & 3);
#pragma unroll
            for (int mi = 0; mi < MI; ++mi) {
                int m = wm0 + mi * 16 + (lane >> 2);
                af[mi][0] = __float_as_uint(At[m * 36 + kk]);
                af[mi][1] = __float_as_uint(At[(m + 8) * 36 + kk]);
                af[mi][2] = __float_as_uint(At[m * 36 + kk + 4]);
                af[mi][3] = __float_as_uint(At[(m + 8) * 36 + kk + 4]);
            }
#pragma unroll
            for (int ni = 0; ni < 4; ++ni) {
                int n = wn0 + ni * 8 + (lane >> 2);
                bf[ni][0] = __float_as_uint(Bt[n * 36 + kk]);
                bf[ni][1] = __float_as_uint(Bt[n * 36 + kk + 4]);
            }
#pragma unroll
            for (int mi = 0; mi < MI; ++mi)
#pragma unroll
                for (int ni = 0; ni < 4; ++ni)
                    mma_tf32(acc[mi][ni], af[mi], bf[ni]);
        }
        __syncthreads();
    }

    float s = (mode >= 2) ? scal[br] : 0.f;
#pragma unroll
    for (int mi = 0; mi < MI; ++mi)
#pragma unroll
        for (int ni = 0; ni < 4; ++ni)
#pragma unroll
            for (int h = 0; h < 2; ++h) {
                int row = m0b + wm0 + mi * 16 + (lane >> 2) + h * 8;
                int col = n0b + wn0 + ni * 8 + (lane & 3) * 2;
                if (row < Mvalid) {
                    size_t off = (size_t)z * dB + (size_t)row * dR + col;
                    float d0 = acc[mi][ni][h * 2], d1 = acc[mi][ni][h * 2 + 1];
                    float2 v;
                    if (mode == 0) {
                        float bi = bias[row];
                        v = make_float2(d0 + bi, d1 + bi);
                    } else if (mode == 2) {
                        float2 x2 = *(const float2*)(xres + off);
                        v = make_float2(2.f * x2.x + s * d0, 2.f * x2.y + s * d1);
                    } else {
                        float2 o = *(const float2*)(D + off);
                        v = make_float2(o.x + s * d0, o.y + s * d1);
                    }
                    *(float2*)(D + off) = v;
                }
            }
}

// ---------------------------------------------------------------------------
// 3xTF32 tensor GEMM (Q,K projection + logits). hi/lo split per operand:
//   a*b ~= ah*bh + ah*bl + al*bh  (effective ~21-bit mantissa).
// Single-buffered 128xNT tiles; 2 CTAs/SM hide fill latency.
// Chunked-K addressing: elem k lives at (k/cb)*cbs + k%cb (cb=0 -> linear).
// Split-K: z = b*CH + ch; k range = [ch*Kc, (ch+1)*Kc).
// mode: 0 = +bias[m] -> D[b=z]; 1 = raw partial -> D[z]
// ---------------------------------------------------------------------------
template<int NT>
__global__ __launch_bounds__(256, 2)
void mma3x_gemm(const float* __restrict__ A, size_t aR, size_t aB, int aCb, size_t aCbs,
                const float* __restrict__ Bp, size_t bR, size_t bB, int bCb, size_t bCbs,
                float* __restrict__ D, size_t dR, size_t dB,
                int Kc, int CH, int Mvalid, int mode, const float* __restrict__ bias) {
    extern __shared__ float sm[];
    float* Ah = sm;
    float* Al = sm + 128 * 36;
    float* Bh = sm + 2 * 128 * 36;
    float* Bl = sm + 2 * 128 * 36 + NT * 36;

    int tid = threadIdx.x, lane = tid & 31, wid = tid >> 5;
    int z = blockIdx.z;
    int b = z / CH, ch = z % CH;
    int m0b = blockIdx.y * 128, n0b = blockIdx.x * NT;
    int kbeg = ch * Kc;

    const float* Ag = A + (size_t)b * aB + (size_t)m0b * aR;
    const float* Bg = Bp + (size_t)b * bB + (size_t)n0b * bR;

    constexpr int WNW = NT / 32;
    constexpr int MI  = NT / 32;
    int wn = wid % WNW, wm = wid / WNW;
    int wm0 = wm * (MI * 16), wn0 = wn * 32;

    float acc[MI][4][4];
#pragma unroll
    for (int a = 0; a < MI; ++a)
#pragma unroll
        for (int bb = 0; bb < 4; ++bb)
#pragma unroll
            for (int c = 0; c < 4; ++c) acc[a][bb][c] = 0.f;

    int nkt = Kc >> 5;
    for (int kt = 0; kt < nkt; ++kt) {
        int kb = kbeg + (kt << 5);
        size_t koA = aCb ? ((size_t)(kb / aCb) * aCbs + (size_t)(kb % aCb)) : (size_t)kb;
        size_t koB = bCb ? ((size_t)(kb / bCb) * bCbs + (size_t)(kb % bCb)) : (size_t)kb;
        __syncthreads();                       // previous tile fully consumed
#pragma unroll
        for (int it = 0; it < 4; ++it) {       // A: 128 rows x 32 k
            int i = tid + it * 256;
            int r = i >> 3, c = (i & 7) << 2;
            int rr = (r < Mvalid) ? r : (Mvalid - 1);   // OOB clamp (dup rows discarded)
            float4 v = *(const float4*)(Ag + (size_t)rr * aR + koA + c);
            float4 hi = make_float4(to_tf32(v.x), to_tf32(v.y), to_tf32(v.z), to_tf32(v.w));
            float4 lo = make_float4(to_tf32(v.x - hi.x), to_tf32(v.y - hi.y),
                                    to_tf32(v.z - hi.z), to_tf32(v.w - hi.w));
            *(float4*)&Ah[r * 36 + c] = hi;
            *(float4*)&Al[r * 36 + c] = lo;
        }
#pragma unroll
        for (int it = 0; it < NT / 32; ++it) { // B: NT rows x 32 k
            int i = tid + it * 256;
            int r = i >> 3, c = (i & 7) << 2;
            float4 v = *(const float4*)(Bg + (size_t)r * bR + koB + c);
            float4 hi = make_float4(to_tf32(v.x), to_tf32(v.y), to_tf32(v.z), to_tf32(v.w));
            float4 lo = make_float4(to_tf32(v.x - hi.x), to_tf32(v.y - hi.y),
                                    to_tf32(v.z - hi.z), to_tf32(v.w - hi.w));
            *(float4*)&Bh[r * 36 + c] = hi;
            *(float4*)&Bl[r * 36 + c] = lo;
        }
        __syncthreads();
#pragma unroll
        for (int ks = 0; ks < 4; ++ks) {
            int kk = ks * 8 + (lane & 3);
            uint32_t ah[MI][4], al[MI][4], bh[4][2], bl[4][2];
#pragma unroll
            for (int mi = 0; mi < MI; ++mi) {
                int m = wm0 + mi * 16 + (lane >> 2);
                ah[mi][0] = __float_as_uint(Ah[m * 36 + kk]);
                ah[mi][1] = __float_as_uint(Ah[(m + 8) * 36 + kk]);
                ah[mi][2] = __float_as_uint(Ah[m * 36 + kk + 4]);
                ah[mi][3] = __float_as_uint(Ah[(m + 8) * 36 + kk + 4]);
                al[mi][0] = __float_as_uint(Al[m * 36 + kk]);
                al[mi][1] = __float_as_uint(Al[(m + 8) * 36 + kk]);
                al[mi][2] = __float_as_uint(Al[m * 36 + kk + 4]);
                al[mi][3] = __float_as_uint(Al[(m + 8) * 36 + kk + 4]);
            }
#pragma unroll
            for (int ni = 0; ni < 4; ++ni) {
                int n = wn0 + ni * 8 + (lane >> 2);
                bh[ni][0] = __float_as_uint(Bh[n * 36 + kk]);
                bh[ni][1] = __float_as_uint(Bh[n * 36 + kk + 4]);
                bl[ni][0] = __float_as_uint(Bl[n * 36 + kk]);
                bl[ni][1] = __float_as_uint(Bl[n * 36 + kk + 4]);
            }
#pragma unroll
            for (int mi = 0; mi < MI; ++mi)
#pragma unroll
                for (int ni = 0; ni < 4; ++ni) {
                    mma_tf32(acc[mi][ni], ah[mi], bh[ni]);
                    mma_tf32(acc[mi][ni], ah[mi], bl[ni]);
                    mma_tf32(acc[mi][ni], al[mi], bh[ni]);
                }
        }
    }

#pragma unroll
    for (int mi = 0; mi < MI; ++mi)
#pragma unroll
        for (int ni = 0; ni < 4; ++ni)
#pragma unroll
            for (int h = 0; h < 2; ++h) {
                int row = m0b + wm0 + mi * 16 + (lane >> 2) + h * 8;
                int col = n0b + wn0 + ni * 8 + (lane & 3) * 2;
                if (row < Mvalid) {
                    size_t off = (mode == 0 ? (size_t)b : (size_t)z) * dB
                               + (size_t)row * dR + col;
                    float d0 = acc[mi][ni][h * 2], d1 = acc[mi][ni][h * 2 + 1];
                    float2 v;
                    if (mode == 0) {
                        float bi = bias[row];
                        v = make_float2(d0 + bi, d1 + bi);
                    } else {
                        v = make_float2(d0, d1);
                    }
                    *(float2*)(D + off) = v;
                }
            }
}

// ---------------------------------------------------------------------------
// Fused split-K reduce + row softmax: att[b,h,:] = softmax(sum_ch part).
// ---------------------------------------------------------------------------
__global__ void reduce_softmax_kernel(int S, int CH) {
    __shared__ float red[128];
    int SS = S * S;
    int b = blockIdx.x / S, h = blockIdx.x % S;
    int t = threadIdx.x;
    const float* base = g_part + (size_t)b * CH * SS + (size_t)h * S + t;
    float v = 0.f;
    for (int ch = 0; ch < CH; ++ch) v += base[(size_t)ch * SS];
    red[t] = v;
    __syncthreads();
    for (int off = S >> 1; off > 0; off >>= 1) {
        if (t < off) red[t] = fmaxf(red[t], red[t + off]);
        __syncthreads();
    }
    float m = red[0];
    __syncthreads();
    float e = expf(v - m);
    red[t] = e;
    __syncthreads();
    for (int off = S >> 1; off > 0; off >>= 1) {
        if (t < off) red[t] += red[t + off];
        __syncthreads();
    }
    g_att[(size_t)b * SS + (size_t)h * S + t] = e / red[0];
}

// ---------------------------------------------------------------------------
// Host orchestration
// ---------------------------------------------------------------------------
static void process_map(const float* x, int S, float* out, int brw, int brh,
                        const float* qw, const float* qb, const float* kw, const float* kb,
                        const float* vw, const float* vb, const float* sc,
                        float* qkv, float* qk, float* xt, float* att,
                        float* part, float* qt, float* kt_, float* wqk, float* bqk) {
    const size_t SS = (size_t)S * S;
    const size_t F  = 32 * (size_t)S;
    const bool big  = (S == 128);
    const int CH = big ? 32 : 16;             // split-K chunks for logits
    const int Kc = (int)F / CH;               // 128 both
    dim3 t32(32, 8);

    // X^T (pixel-major [SS][C]) for projections' B operand
    transpose_kernel<<<dim3(SS / 32, C_ / 32, B_), t32>>>(x, xt, C_, (int)SS,
                                                          1, C_ * SS, 0, C_ * SS, 0);

    // Stack Q/K weights+bias of BOTH branches: [Qw;Kw;Qh;Kh] = 128 x 256
    cudaMemcpyAsync(wqk,          qw + (size_t)brw * 32 * C_, 32 * C_ * 4, cudaMemcpyDeviceToDevice);
    cudaMemcpyAsync(wqk + 32*C_,  kw + (size_t)brw * 32 * C_, 32 * C_ * 4, cudaMemcpyDeviceToDevice);
    cudaMemcpyAsync(wqk + 64*C_,  qw + (size_t)brh * 32 * C_, 32 * C_ * 4, cudaMemcpyDeviceToDevice);
    cudaMemcpyAsync(wqk + 96*C_,  kw + (size_t)brh * 32 * C_, 32 * C_ * 4, cudaMemcpyDeviceToDevice);
    cudaMemcpyAsync(bqk,      qb + (size_t)brw * 32, 32 * 4, cudaMemcpyDeviceToDevice);
    cudaMemcpyAsync(bqk + 32, kb + (size_t)brw * 32, 32 * 4, cudaMemcpyDeviceToDevice);
    cudaMemcpyAsync(bqk + 64, qb + (size_t)brh * 32, 32 * 4, cudaMemcpyDeviceToDevice);
    cudaMemcpyAsync(bqk + 96, kb + (size_t)brh * 32, 32 * 4, cudaMemcpyDeviceToDevice);

    // QK projection (both branches, 3xTF32): g_qk[b][128][SS]
    mma3x_gemm<128><<<dim3(SS / 128, 1, B_), 256, 73728>>>(
        wqk, C_, 0, 0, 0,
        xt, C_, C_ * SS, 0, 0,
        qk, SS, (size_t)128 * SS,
        C_, 1, 128, 0, bqk);

    for (int pass = 0; pass < 2; ++pass) {
        int br = pass ? brh : brw;
        // V projection (plain tf32), A = vw[br] directly
        mma_gemm<128><<<dim3(SS / 128, 2, B_), 256, 73728>>>(
            vw + (size_t)br * C_ * C_, C_, 0, 1,
            xt, C_, C_ * SS,
            qkv + 64 * SS, SS, (size_t)MR * SS,
            C_, 256, 0, vb + (size_t)br * C_, nullptr, sc, br);

        if (pass == 0) {
            // logits-W: need Q^T,K^T ([S][F]); Q=qk rows 0-31, K=rows 32-63
            transpose_kernel<<<dim3(S / 32, F / 32, B_), t32>>>(
                qk, qt, (int)F, S, 1, (size_t)128 * SS, 0, (size_t)S * F, 0);
            transpose_kernel<<<dim3(S / 32, F / 32, B_), t32>>>(
                qk + 32 * SS, kt_, (int)F, S, 1, (size_t)128 * SS, 0, (size_t)S * F, 0);
            if (big)
                mma3x_gemm<128><<<dim3(1, 1, B_ * CH), 256, 73728>>>(
                    qt, F, (size_t)S * F, 0, 0,
                    kt_, F, (size_t)S * F, 0, 0,
                    part, S, SS, Kc, CH, S, 1, nullptr);
            else
                mma3x_gemm<64><<<dim3(1, 1, B_ * CH), 256, 55296>>>(
                    qt, F, (size_t)S * F, 0, 0,
                    kt_, F, (size_t)S * F, 0, 0,
                    part, S, SS, Kc, CH, S, 1, nullptr);
        } else {
            // logits-H: chunked-K direct on qk layout (Qh rows 64.., Kh rows 96..)
            if (big)
                mma3x_gemm<128><<<dim3(1, 1, B_ * CH), 256, 73728>>>(
                    qk + 64 * SS, S, (size_t)128 * SS, S, SS,
                    qk + 96 * SS, S, (size_t)128 * SS, S, SS,
                    part, S, SS, Kc, CH, S, 1, nullptr);
            else
                mma3x_gemm<64><<<dim3(1, 1, B_ * CH), 256, 55296>>>(
                    qk + 64 * SS, S, (size_t)128 * SS, S, SS,
                    qk + 96 * SS, S, (size_t)128 * SS, S, SS,
                    part, S, SS, Kc, CH, S, 1, nullptr);
        }
        reduce_softmax_kernel<<<B_ * S, S>>>(S, CH);

        if (pass == 0) {
            // apply-W: out = 2x + s * V @ A^T
            if (big)
                mma_gemm<128><<<dim3(1, C_ * S / 128, B_), 256, 73728>>>(
                    qkv + 64 * SS, S, (size_t)MR * SS, 1,
                    att, S, SS,
                    out, S, (size_t)C_ * SS,
                    S, C_ * S, 2, nullptr, x, sc, br);
            else
                mma_gemm<64><<<dim3(1, C_ * S / 128, B_), 256, 55296>>>(
                    qkv + 64 * SS, S, (size_t)MR * SS, 1,
                    att, S, SS,
                    out, S, (size_t)C_ * SS,
                    S, C_ * S, 2, nullptr, x, sc, br);
        } else {
            // spatial transpose of V into xt (Xt no longer needed)
            transpose_kernel<<<dim3(S / 32, S / 32, B_ * C_), t32>>>(
                qkv + 64 * SS, xt, S, S, C_, (size_t)MR * SS, SS, (size_t)C_ * SS, SS);
            // apply-H: out += s * A @ V
            if (big)
                mma_gemm<128><<<dim3(1, 1, B_ * C_), 256, 73728>>>(
                    att, S, SS, C_,
                    xt, S, SS,
                    out, S, SS,
                    S, S, 3, nullptr, nullptr, sc, br);
            else
                mma_gemm<64><<<dim3(1, 1, B_ * C_), 256, 55296>>>(
                    att, S, SS, C_,
                    xt, S, SS,
                    out, S, SS,
                    S, S, 3, nullptr, nullptr, sc, br);
        }
    }
}

extern "C" void kernel_launch(void* const* d_in, const int* in_sizes, int n_in,
                              void* d_out, int out_size) {
    const float* tmap = (const float*)d_in[0];
    const float* smap = (const float*)d_in[1];
    const float* qw   = (const float*)d_in[2];
    const float* qb   = (const float*)d_in[3];
    const float* kw   = (const float*)d_in[4];
    const float* kb   = (const float*)d_in[5];
    const float* vw   = (const float*)d_in[6];
    const float* vb   = (const float*)d_in[7];
    const float* sc   = (const float*)d_in[8];

    cudaFuncSetAttribute(mma_gemm<128>,   cudaFuncAttributeMaxDynamicSharedMemorySize, 73728);
    cudaFuncSetAttribute(mma_gemm<64>,    cudaFuncAttributeMaxDynamicSharedMemorySize, 55296);
    cudaFuncSetAttribute(mma3x_gemm<128>, cudaFuncAttributeMaxDynamicSharedMemorySize, 73728);
    cudaFuncSetAttribute(mma3x_gemm<64>,  cudaFuncAttributeMaxDynamicSharedMemorySize, 55296);

    void *p_qkv, *p_qk, *p_xt, *p_att, *p_part, *p_qt, *p_kt, *p_wqk, *p_bqk;
    cudaGetSymbolAddress(&p_qkv,  g_qkv);
    cudaGetSymbolAddress(&p_qk,   g_qk);
    cudaGetSymbolAddress(&p_xt,   g_xt);
    cudaGetSymbolAddress(&p_att,  g_att);
    cudaGetSymbolAddress(&p_part, g_part);
    cudaGetSymbolAddress(&p_qt,   g_qt);
    cudaGetSymbolAddress(&p_kt,   g_kt);
    cudaGetSymbolAddress(&p_wqk,  g_wqk);
    cudaGetSymbolAddress(&p_bqk,  g_bqk);

    float* tout = (float*)d_out;
    float* sout = tout + (size_t)B_ * C_ * 64 * 64;

    process_map(tmap, 64,  tout, 0, 2, qw, qb, kw, kb, vw, vb, sc,
                (float*)p_qkv, (float*)p_qk, (float*)p_xt, (float*)p_att,
                (float*)p_part, (float*)p_qt, (float*)p_kt, (float*)p_wqk, (float*)p_bqk);
    process_map(smap, 128, sout, 1, 3, qw, qb, kw, kb, vw, vb, sc,
                (float*)p_qkv, (float*)p_qk, (float*)p_xt, (float*)p_att,
                (float*)p_part, (float*)p_qt, (float*)p_kt, (float*)p_wqk, (float*)p_bqk);
}

// round 15
// speedup vs baseline: 2.8782x; 1.1403x over previous
#include <cuda_runtime.h>
#include <cstdint>

// ===========================================================================
// PAM module on GB300 (base sm_103 target -> mma.sync tf32 tensor cores).
// 3xTF32 mma for Q,K projection + logits; plain tf32 mma elsewhere.
// ZERO transpose kernels: GEMMs consume k-major global operands directly via
// k-major smem tiles (row stride NT+8 -> conflict-free fragment loads).
// B=16, C=256, C8=32. Template 64x64, scene 128x128.
// ===========================================================================

#define B_  16
#define C_  256
#define MR  320   // V stored at rows 64..319 of this stride

// --------------------------- device scratch --------------------------------
__device__ float g_qkv [(size_t)B_ * MR * 128 * 128];    // V storage
__device__ float g_qk  [(size_t)B_ * 128 * 128 * 128];   // Qw,Kw,Qh,Kh (32 rows each)
__device__ float g_att [(size_t)B_ * 128 * 128];
__device__ float g_part[(size_t)32 * B_ * 128 * 128];    // split-K logits partials
__device__ float g_wqk [128 * C_];                       // stacked QK weights
__device__ float g_bqk [128];                            // stacked QK bias

// --------------------------- PTX helpers -----------------------------------
__device__ __forceinline__ void cp16(void* dst, const void* src) {
    uint32_t d = (uint32_t)__cvta_generic_to_shared(dst);
    asm volatile("cp.async.cg.shared.global [%0], [%1], 16;" :: "r"(d), "l"(src));
}
__device__ __forceinline__ void cp_commit() {
    asm volatile("cp.async.commit_group;" ::: "memory");
}
__device__ __forceinline__ void mma_tf32(float* c, const uint32_t* a, const uint32_t* b) {
    asm volatile("mma.sync.aligned.m16n8k8.row.col.f32.tf32.tf32.f32 "
        "{%0,%1,%2,%3}, {%4,%5,%6,%7}, {%8,%9}, {%0,%1,%2,%3};"
        : "+f"(c[0]), "+f"(c[1]), "+f"(c[2]), "+f"(c[3])
        : "r"(a[0]), "r"(a[1]), "r"(a[2]), "r"(a[3]), "r"(b[0]), "r"(b[1]));
}
__device__ __forceinline__ float to_tf32(float x) {
    float y; asm("cvt.rna.tf32.f32 %0, %1;" : "=f"(y) : "f"(x)); return y;
}

// ---------------------------------------------------------------------------
// Plain tf32 GEMM: D[z][m][n] = sum_k A[m][k]*B(k,n)  (+epilogue)
//   A: standard [m][k] global. B: BKM ? [k][n] global : [n][k] global.
//   B addr: Bp + (z/bZ1)*bBa + (z%bZ1)*bBb (+ k*bR or n*bR).
//   mode: 0 = +bias[m]; 2 = out = 2*x + s*d; 3 = out += s*d
// ---------------------------------------------------------------------------
template<int NT, int BKM>
__global__ __launch_bounds__(256, 2)
void mma_gemm(const float* __restrict__ A, size_t aR, size_t aB, int aZ,
              const float* __restrict__ Bp, size_t bR, int bZ1, size_t bBa, size_t bBb,
              float* __restrict__ D, size_t dR, size_t dB,
              int K, int Mvalid, int mode,
              const float* __restrict__ bias, const float* __restrict__ xres,
              const float* __restrict__ scal, int br) {
    constexpr int BS  = NT + 8;          // k-major B row stride
    constexpr int BSZ = NT * 36;         // per-buffer B floats (>= 32*BS)
    extern __shared__ float sm[];
    float* Asm[2] = { sm, sm + 128 * 36 };
    float* Bsm[2] = { sm + 2 * 128 * 36, sm + 2 * 128 * 36 + BSZ };

    int tid = threadIdx.x, lane = tid & 31, wid = tid >> 5;
    int z = blockIdx.z;
    int m0b = blockIdx.y * 128, n0b = blockIdx.x * NT;

    const float* Ag = A + (size_t)(z / aZ) * aB + (size_t)m0b * aR;
    const float* Bg = Bp + (size_t)(z / bZ1) * bBa + (size_t)(z % bZ1) * bBb
                    + (BKM ? (size_t)n0b : (size_t)n0b * bR);

    auto fill = [&](int buf, int k0) {
#pragma unroll
        for (int it = 0; it < 4; ++it) {            // A: 128 rows x 32 k
            int i = tid + it * 256;
            int r = i >> 3, c = (i & 7) << 2;
            cp16(&Asm[buf][r * 36 + c], Ag + (size_t)r * aR + k0 + c);
        }
#pragma unroll
        for (int it = 0; it < NT / 32; ++it) {      // B: 32 k x NT n (either layout)
            int i = tid + it * 256;
            if (BKM) {
                int k = i / (NT / 4), q = i % (NT / 4);
                cp16(&Bsm[buf][k * BS + q * 4], Bg + (size_t)(k0 + k) * bR + q * 4);
            } else {
                int r = i >> 3, c = (i & 7) << 2;
                cp16(&Bsm[buf][r * 36 + c], Bg + (size_t)r * bR + k0 + c);
            }
        }
        cp_commit();
    };

    constexpr int WNW = NT / 32;
    constexpr int MI  = NT / 32;
    int wn = wid % WNW, wm = wid / WNW;
    int wm0 = wm * (MI * 16), wn0 = wn * 32;

    float acc[MI][4][4];
#pragma unroll
    for (int a = 0; a < MI; ++a)
#pragma unroll
        for (int b = 0; b < 4; ++b)
#pragma unroll
            for (int c = 0; c < 4; ++c) acc[a][b][c] = 0.f;

    int nkt = K >> 5;
    fill(0, 0);
    for (int kt = 0; kt < nkt; ++kt) {
        int buf = kt & 1;
        if (kt + 1 < nkt) {
            fill(buf ^ 1, (kt + 1) << 5);
            asm volatile("cp.async.wait_group 1;" ::: "memory");
        } else {
            asm volatile("cp.async.wait_group 0;" ::: "memory");
        }
        __syncthreads();
        const float* At = Asm[buf];
        const float* Bt = Bsm[buf];
#pragma unroll
        for (int ks = 0; ks < 4; ++ks) {
            uint32_t af[MI][4], bf[4][2];
            int kk = ks * 8 + (lane & 3);
#pragma unroll
            for (int mi = 0; mi < MI; ++mi) {
                int m = wm0 + mi * 16 + (lane >> 2);
                af[mi][0] = __float_as_uint(At[m * 36 + kk]);
                af[mi][1] = __float_as_uint(At[(m + 8) * 36 + kk]);
                af[mi][2] = __float_as_uint(At[m * 36 + kk + 4]);
                af[mi][3] = __float_as_uint(At[(m + 8) * 36 + kk + 4]);
            }
#pragma unroll
            for (int ni = 0; ni < 4; ++ni) {
                int n = wn0 + ni * 8 + (lane >> 2);
                if (BKM) {
                    bf[ni][0] = __float_as_uint(Bt[kk * BS + n]);
                    bf[ni][1] = __float_as_uint(Bt[(kk + 4) * BS + n]);
                } else {
                    bf[ni][0] = __float_as_uint(Bt[n * 36 + kk]);
                    bf[ni][1] = __float_as_uint(Bt[n * 36 + kk + 4]);
                }
            }
#pragma unroll
            for (int mi = 0; mi < MI; ++mi)
#pragma unroll
                for (int ni = 0; ni < 4; ++ni)
                    mma_tf32(acc[mi][ni], af[mi], bf[ni]);
        }
        __syncthreads();
    }

    float s = (mode >= 2) ? scal[br] : 0.f;
#pragma unroll
    for (int mi = 0; mi < MI; ++mi)
#pragma unroll
        for (int ni = 0; ni < 4; ++ni)
#pragma unroll
            for (int h = 0; h < 2; ++h) {
                int row = m0b + wm0 + mi * 16 + (lane >> 2) + h * 8;
                int col = n0b + wn0 + ni * 8 + (lane & 3) * 2;
                if (row < Mvalid) {
                    size_t off = (size_t)z * dB + (size_t)row * dR + col;
                    float d0 = acc[mi][ni][h * 2], d1 = acc[mi][ni][h * 2 + 1];
                    float2 v;
                    if (mode == 0) {
                        float bi = bias[row];
                        v = make_float2(d0 + bi, d1 + bi);
                    } else if (mode == 2) {
                        float2 x2 = *(const float2*)(xres + off);
                        v = make_float2(2.f * x2.x + s * d0, 2.f * x2.y + s * d1);
                    } else {
                        float2 o = *(const float2*)(D + off);
                        v = make_float2(o.x + s * d0, o.y + s * d1);
                    }
                    *(float2*)(D + off) = v;
                }
            }
}

// ---------------------------------------------------------------------------
// 3xTF32 GEMM (Q,K projection + logits). hi/lo split, ~21-bit mantissa.
// AKM: A global is [k][m] (k-row stride aR); else [m][k] (chunked via aCb/aCbs).
// BKM: B global is [k][n]; else [n][k] (chunked via bCb/bCbs).
// Split-K: z = b*CH + ch. mode: 0 = +bias[m] -> D[b]; 1 = raw partial -> D[z].
// ---------------------------------------------------------------------------
template<int NT, int AKM, int BKM>
__global__ __launch_bounds__(256, 2)
void mma3x_gemm(const float* __restrict__ A, size_t aR, size_t aB, int aCb, size_t aCbs,
                const float* __restrict__ Bp, size_t bR, size_t bB, int bCb, size_t bCbs,
                float* __restrict__ D, size_t dR, size_t dB,
                int Kc, int CH, int Mvalid, int mode, const float* __restrict__ bias) {
    constexpr int BS  = NT + 8;
    constexpr int BSZ = NT * 36;
    extern __shared__ float sm[];
    float* Ah = sm;
    float* Al = sm + 128 * 36;
    float* Bh = sm + 2 * 128 * 36;
    float* Bl = sm + 2 * 128 * 36 + BSZ;

    int tid = threadIdx.x, lane = tid & 31, wid = tid >> 5;
    int z = blockIdx.z;
    int b = z / CH, ch = z % CH;
    int m0b = blockIdx.y * 128, n0b = blockIdx.x * NT;
    int kbeg = ch * Kc;

    const float* Ag = A + (size_t)b * aB + (AKM ? (size_t)m0b : (size_t)m0b * aR);
    const float* Bg = Bp + (size_t)b * bB + (BKM ? (size_t)n0b : (size_t)n0b * bR);

    constexpr int WNW = NT / 32;
    constexpr int MI  = NT / 32;
    int wn = wid % WNW, wm = wid / WNW;
    int wm0 = wm * (MI * 16), wn0 = wn * 32;

    float acc[MI][4][4];
#pragma unroll
    for (int a = 0; a < MI; ++a)
#pragma unroll
        for (int bb = 0; bb < 4; ++bb)
#pragma unroll
            for (int c = 0; c < 4; ++c) acc[a][bb][c] = 0.f;

    int nkt = Kc >> 5;
    for (int kt = 0; kt < nkt; ++kt) {
        int kb = kbeg + (kt << 5);
        __syncthreads();                       // previous tile fully consumed
        // ---- A tile ----
#pragma unroll
        for (int it = 0; it < 4; ++it) {
            int i = tid + it * 256;
            float4 v;
            int sa;
            if (AKM) {                         // [k][m] global -> k-major smem
                int k = i >> 5, q = i & 31;
                int m4 = q * 4;
                if (m4 > Mvalid - 4) m4 = Mvalid - 4;
                v = *(const float4*)(Ag + (size_t)(kb + k) * aR + m4);
                sa = k * 136 + q * 4;
            } else {                           // [m][k] global -> m-major smem
                int r = i >> 3, c = (i & 7) << 2;
                int rr = (r < Mvalid) ? r : (Mvalid - 1);
                size_t ko = aCb ? ((size_t)(kb / aCb) * aCbs + (size_t)(kb % aCb))
                                : (size_t)kb;
                v = *(const float4*)(Ag + (size_t)rr * aR + ko + c);
                sa = r * 36 + c;
            }
            float4 hi = make_float4(to_tf32(v.x), to_tf32(v.y), to_tf32(v.z), to_tf32(v.w));
            float4 lo = make_float4(to_tf32(v.x - hi.x), to_tf32(v.y - hi.y),
                                    to_tf32(v.z - hi.z), to_tf32(v.w - hi.w));
            *(float4*)&Ah[sa] = hi;
            *(float4*)&Al[sa] = lo;
        }
        // ---- B tile ----
#pragma unroll
        for (int it = 0; it < NT / 32; ++it) {
            int i = tid + it * 256;
            float4 v;
            int sa;
            if (BKM) {
                int k = i / (NT / 4), q = i % (NT / 4);
                v = *(const float4*)(Bg + (size_t)(kb + k) * bR + q * 4);
                sa = k * BS + q * 4;
            } else {
                int r = i >> 3, c = (i & 7) << 2;
                size_t ko = bCb ? ((size_t)(kb / bCb) * bCbs + (size_t)(kb % bCb))
                                : (size_t)kb;
                v = *(const float4*)(Bg + (size_t)r * bR + ko + c);
                sa = r * 36 + c;
            }
            float4 hi = make_float4(to_tf32(v.x), to_tf32(v.y), to_tf32(v.z), to_tf32(v.w));
            float4 lo = make_float4(to_tf32(v.x - hi.x), to_tf32(v.y - hi.y),
                                    to_tf32(v.z - hi.z), to_tf32(v.w - hi.w));
            *(float4*)&Bh[sa] = hi;
            *(float4*)&Bl[sa] = lo;
        }
        __syncthreads();
#pragma unroll
        for (int ks = 0; ks < 4; ++ks) {
            int kk = ks * 8 + (lane & 3);
            uint32_t ah[MI][4], al[MI][4], bh[4][2], bl[4][2];
#pragma unroll
            for (int mi = 0; mi < MI; ++mi) {
                int m = wm0 + mi * 16 + (lane >> 2);
                if (AKM) {
                    ah[mi][0] = __float_as_uint(Ah[kk * 136 + m]);
                    ah[mi][1] = __float_as_uint(Ah[kk * 136 + m + 8]);
                    ah[mi][2] = __float_as_uint(Ah[(kk + 4) * 136 + m]);
                    ah[mi][3] = __float_as_uint(Ah[(kk + 4) * 136 + m + 8]);
                    al[mi][0] = __float_as_uint(Al[kk * 136 + m]);
                    al[mi][1] = __float_as_uint(Al[kk * 136 + m + 8]);
                    al[mi][2] = __float_as_uint(Al[(kk + 4) * 136 + m]);
                    al[mi][3] = __float_as_uint(Al[(kk + 4) * 136 + m + 8]);
                } else {
                    ah[mi][0] = __float_as_uint(Ah[m * 36 + kk]);
                    ah[mi][1] = __float_as_uint(Ah[(m + 8) * 36 + kk]);
                    ah[mi][2] = __float_as_uint(Ah[m * 36 + kk + 4]);
                    ah[mi][3] = __float_as_uint(Ah[(m + 8) * 36 + kk + 4]);
                    al[mi][0] = __float_as_uint(Al[m * 36 + kk]);
                    al[mi][1] = __float_as_uint(Al[(m + 8) * 36 + kk]);
                    al[mi][2] = __float_as_uint(Al[m * 36 + kk + 4]);
                    al[mi][3] = __float_as_uint(Al[(m + 8) * 36 + kk + 4]);
                }
            }
#pragma unroll
            for (int ni = 0; ni < 4; ++ni) {
                int n = wn0 + ni * 8 + (lane >> 2);
                if (BKM) {
                    bh[ni][0] = __float_as_uint(Bh[kk * BS + n]);
                    bh[ni][1] = __float_as_uint(Bh[(kk + 4) * BS + n]);
                    bl[ni][0] = __float_as_uint(Bl[kk * BS + n]);
                    bl[ni][1] = __float_as_uint(Bl[(kk + 4) * BS + n]);
                } else {
                    bh[ni][0] = __float_as_uint(Bh[n * 36 + kk]);
                    bh[ni][1] = __float_as_uint(Bh[n * 36 + kk + 4]);
                    bl[ni][0] = __float_as_uint(Bl[n * 36 + kk]);
                    bl[ni][1] = __float_as_uint(Bl[n * 36 + kk + 4]);
                }
            }
#pragma unroll
            for (int mi = 0; mi < MI; ++mi)
#pragma unroll
                for (int ni = 0; ni < 4; ++ni) {
                    mma_tf32(acc[mi][ni], ah[mi], bh[ni]);
                    mma_tf32(acc[mi][ni], ah[mi], bl[ni]);
                    mma_tf32(acc[mi][ni], al[mi], bh[ni]);
                }
        }
    }

#pragma unroll
    for (int mi = 0; mi < MI; ++mi)
#pragma unroll
        for (int ni = 0; ni < 4; ++ni)
#pragma unroll
            for (int h = 0; h < 2; ++h) {
                int row = m0b + wm0 + mi * 16 + (lane >> 2) + h * 8;
                int col = n0b + wn0 + ni * 8 + (lane & 3) * 2;
                if (row < Mvalid) {
                    size_t off = (mode == 0 ? (size_t)b : (size_t)z) * dB
                               + (size_t)row * dR + col;
                    float d0 = acc[mi][ni][h * 2], d1 = acc[mi][ni][h * 2 + 1];
                    float2 v;
                    if (mode == 0) {
                        float bi = bias[row];
                        v = make_float2(d0 + bi, d1 + bi);
                    } else {
                        v = make_float2(d0, d1);
                    }
                    *(float2*)(D + off) = v;
                }
            }
}

// ---------------------------------------------------------------------------
// Fused split-K reduce + row softmax: att[b,h,:] = softmax(sum_ch part).
// ---------------------------------------------------------------------------
__global__ void reduce_softmax_kernel(int S, int CH) {
    __shared__ float red[128];
    int SS = S * S;
    int b = blockIdx.x / S, h = blockIdx.x % S;
    int t = threadIdx.x;
    const float* base = g_part + (size_t)b * CH * SS + (size_t)h * S + t;
    float v = 0.f;
    for (int ch = 0; ch < CH; ++ch) v += base[(size_t)ch * SS];
    red[t] = v;
    __syncthreads();
    for (int off = S >> 1; off > 0; off >>= 1) {
        if (t < off) red[t] = fmaxf(red[t], red[t + off]);
        __syncthreads();
    }
    float m = red[0];
    __syncthreads();
    float e = expf(v - m);
    red[t] = e;
    __syncthreads();
    for (int off = S >> 1; off > 0; off >>= 1) {
        if (t < off) red[t] += red[t + off];
        __syncthreads();
    }
    g_att[(size_t)b * SS + (size_t)h * S + t] = e / red[0];
}

// ---------------------------------------------------------------------------
// Host orchestration
// ---------------------------------------------------------------------------
static void process_map(const float* x, int S, float* out, int brw, int brh,
                        const float* qw, const float* qb, const float* kw, const float* kb,
                        const float* vw, const float* vb, const float* sc,
                        float* qkv, float* qk, float* att, float* part,
                        float* wqk, float* bqk) {
    const size_t SS = (size_t)S * S;
    const size_t F  = 32 * (size_t)S;
    const bool big  = (S == 128);
    const int CH = big ? 32 : 16;             // split-K chunks for logits
    const int Kc = (int)F / CH;               // 128 both

    // Stack Q/K weights+bias of BOTH branches: [Qw;Kw;Qh;Kh] = 128 x 256
    cudaMemcpyAsync(wqk,          qw + (size_t)brw * 32 * C_, 32 * C_ * 4, cudaMemcpyDeviceToDevice);
    cudaMemcpyAsync(wqk + 32*C_,  kw + (size_t)brw * 32 * C_, 32 * C_ * 4, cudaMemcpyDeviceToDevice);
    cudaMemcpyAsync(wqk + 64*C_,  qw + (size_t)brh * 32 * C_, 32 * C_ * 4, cudaMemcpyDeviceToDevice);
    cudaMemcpyAsync(wqk + 96*C_,  kw + (size_t)brh * 32 * C_, 32 * C_ * 4, cudaMemcpyDeviceToDevice);
    cudaMemcpyAsync(bqk,      qb + (size_t)brw * 32, 32 * 4, cudaMemcpyDeviceToDevice);
    cudaMemcpyAsync(bqk + 32, kb + (size_t)brw * 32, 32 * 4, cudaMemcpyDeviceToDevice);
    cudaMemcpyAsync(bqk + 64, qb + (size_t)brh * 32, 32 * 4, cudaMemcpyDeviceToDevice);
    cudaMemcpyAsync(bqk + 96, kb + (size_t)brh * 32, 32 * 4, cudaMemcpyDeviceToDevice);

    // QK projection (both branches, 3xTF32), B = X directly (k-major [C][SS])
    mma3x_gemm<128, 0, 1><<<dim3(SS / 128, 1, B_), 256, 73728>>>(
        wqk, C_, 0, 0, 0,
        x, SS, C_ * SS, 0, 0,
        qk, SS, (size_t)128 * SS,
        C_, 1, 128, 0, bqk);

    for (int pass = 0; pass < 2; ++pass) {
        int br = pass ? brh : brw;
        // V projection (plain tf32), A = vw[br], B = X directly (k-major)
        mma_gemm<128, 1><<<dim3(SS / 128, 2, B_), 256, 73728>>>(
            vw + (size_t)br * C_ * C_, C_, 0, 1,
            x, SS, 1, C_ * SS, 0,
            qkv + 64 * SS, SS, (size_t)MR * SS,
            C_, 256, 0, vb + (size_t)br * C_, nullptr, sc, br);

        if (pass == 0) {
            // logits-W: A = Q (k-major [o*S+h][w]), B = K (k-major), direct
            if (big)
                mma3x_gemm<128, 1, 1><<<dim3(1, 1, B_ * CH), 256, 73728>>>(
                    qk, S, (size_t)128 * SS, 0, 0,
                    qk + 32 * SS, S, (size_t)128 * SS, 0, 0,
                    part, S, SS, Kc, CH, S, 1, nullptr);
            else
                mma3x_gemm<64, 1, 1><<<dim3(1, 1, B_ * CH), 256, 55296>>>(
                    qk, S, (size_t)128 * SS, 0, 0,
                    qk + 32 * SS, S, (size_t)128 * SS, 0, 0,
                    part, S, SS, Kc, CH, S, 1, nullptr);
        } else {
            // logits-H: chunked-K on projected layout (Qh rows 64.., Kh rows 96..)
            if (big)
                mma3x_gemm<128, 0, 0><<<dim3(1, 1, B_ * CH), 256, 73728>>>(
                    qk + 64 * SS, S, (size_t)128 * SS, S, SS,
                    qk + 96 * SS, S, (size_t)128 * SS, S, SS,
                    part, S, SS, Kc, CH, S, 1, nullptr);
            else
                mma3x_gemm<64, 0, 0><<<dim3(1, 1, B_ * CH), 256, 55296>>>(
                    qk + 64 * SS, S, (size_t)128 * SS, S, SS,
                    qk + 96 * SS, S, (size_t)128 * SS, S, SS,
                    part, S, SS, Kc, CH, S, 1, nullptr);
        }
        reduce_softmax_kernel<<<B_ * S, S>>>(S, CH);

        if (pass == 0) {
            // apply-W: out = 2x + s * V @ att^T (both operands n-major)
            if (big)
                mma_gemm<128, 0><<<dim3(1, C_ * S / 128, B_), 256, 73728>>>(
                    qkv + 64 * SS, S, (size_t)MR * SS, 1,
                    att, S, 1, SS, 0,
                    out, S, (size_t)C_ * SS,
                    S, C_ * S, 2, nullptr, x, sc, br);
            else
                mma_gemm<64, 0><<<dim3(1, C_ * S / 128, B_), 256, 55296>>>(
                    qkv + 64 * SS, S, (size_t)MR * SS, 1,
                    att, S, 1, SS, 0,
                    out, S, (size_t)C_ * SS,
                    S, C_ * S, 2, nullptr, x, sc, br);
        } else {
            // apply-H: out += s * att @ V, B = V[c] directly (k-major [v][w])
            if (big)
                mma_gemm<128, 1><<<dim3(1, 1, B_ * C_), 256, 73728>>>(
                    att, S, SS, C_,
                    qkv + 64 * SS, S, C_, (size_t)MR * SS, SS,
                    out, S, SS,
                    S, S, 3, nullptr, nullptr, sc, br);
            else
                mma_gemm<64, 1><<<dim3(1, 1, B_ * C_), 256, 55296>>>(
                    att, S, SS, C_,
                    qkv + 64 * SS, S, C_, (size_t)MR * SS, SS,
                    out, S, SS,
                    S, S, 3, nullptr, nullptr, sc, br);
        }
    }
}

extern "C" void kernel_launch(void* const* d_in, const int* in_sizes, int n_in,
                              void* d_out, int out_size) {
    const float* tmap = (const float*)d_in[0];
    const float* smap = (const float*)d_in[1];
    const float* qw   = (const float*)d_in[2];
    const float* qb   = (const float*)d_in[3];
    const float* kw   = (const float*)d_in[4];
    const float* kb   = (const float*)d_in[5];
    const float* vw   = (const float*)d_in[6];
    const float* vb   = (const float*)d_in[7];
    const float* sc   = (const float*)d_in[8];

    cudaFuncSetAttribute(mma_gemm<128, 0>,      cudaFuncAttributeMaxDynamicSharedMemorySize, 73728);
    cudaFuncSetAttribute(mma_gemm<128, 1>,      cudaFuncAttributeMaxDynamicSharedMemorySize, 73728);
    cudaFuncSetAttribute(mma_gemm<64, 0>,       cudaFuncAttributeMaxDynamicSharedMemorySize, 55296);
    cudaFuncSetAttribute(mma_gemm<64, 1>,       cudaFuncAttributeMaxDynamicSharedMemorySize, 55296);
    cudaFuncSetAttribute(mma3x_gemm<128, 0, 1>, cudaFuncAttributeMaxDynamicSharedMemorySize, 73728);
    cudaFuncSetAttribute(mma3x_gemm<128, 1, 1>, cudaFuncAttributeMaxDynamicSharedMemorySize, 73728);
    cudaFuncSetAttribute(mma3x_gemm<128, 0, 0>, cudaFuncAttributeMaxDynamicSharedMemorySize, 73728);
    cudaFuncSetAttribute(mma3x_gemm<64, 1, 1>,  cudaFuncAttributeMaxDynamicSharedMemorySize, 55296);
    cudaFuncSetAttribute(mma3x_gemm<64, 0, 0>,  cudaFuncAttributeMaxDynamicSharedMemorySize, 55296);

    void *p_qkv, *p_qk, *p_att, *p_part, *p_wqk, *p_bqk;
    cudaGetSymbolAddress(&p_qkv,  g_qkv);
    cudaGetSymbolAddress(&p_qk,   g_qk);
    cudaGetSymbolAddress(&p_att,  g_att);
    cudaGetSymbolAddress(&p_part, g_part);
    cudaGetSymbolAddress(&p_wqk,  g_wqk);
    cudaGetSymbolAddress(&p_bqk,  g_bqk);

    float* tout = (float*)d_out;
    float* sout = tout + (size_t)B_ * C_ * 64 * 64;

    process_map(tmap, 64,  tout, 0, 2, qw, qb, kw, kb, vw, vb, sc,
                (float*)p_qkv, (float*)p_qk, (float*)p_att,
                (float*)p_part, (float*)p_wqk, (float*)p_bqk);
    process_map(smap, 128, sout, 1, 3, qw, qb, kw, kb, vw, vb, sc,
                (float*)p_qkv, (float*)p_qk, (float*)p_att,
                (float*)p_part, (float*)p_wqk, (float*)p_bqk);
}

// round 16
// speedup vs baseline: 3.0463x; 1.0584x over previous
#include <cuda_runtime.h>
#include <cstdint>

// ===========================================================================
// PAM module on GB300 (base sm_103 target -> mma.sync tf32 tensor cores).
// 3xTF32 mma for Q,K projection + logits; plain tf32 mma elsewhere.
// Zero transposes (k-major smem tiles); template & scene maps overlapped on
// two streams (capture-compatible event fork/join); V proj fused M=512.
// B=16, C=256, C8=32. Template 64x64, scene 128x128.
// ===========================================================================

#define B_   16
#define C_   256
#define SS_T 4096     // 64*64
#define SS_S 16384    // 128*128

// --------------------------- device scratch (template region first) --------
__device__ float g_v   [(size_t)B_ * 512 * (SS_T + SS_S)];   // V0(256)+V1(256) rows
__device__ float g_qk  [(size_t)B_ * 128 * (SS_T + SS_S)];   // Qw,Kw,Qh,Kh
__device__ float g_att [(size_t)B_ * (SS_T + SS_S)];
__device__ float g_part[(size_t)B_ * (16 * SS_T + 32 * SS_S)];
__device__ float g_wqk [2 * 128 * C_];
__device__ float g_bqk [2 * 128];
__device__ float g_wv  [2 * 512 * C_];
__device__ float g_bv  [2 * 512];

// --------------------------- PTX helpers -----------------------------------
__device__ __forceinline__ void cp16(void* dst, const void* src) {
    uint32_t d = (uint32_t)__cvta_generic_to_shared(dst);
    asm volatile("cp.async.cg.shared.global [%0], [%1], 16;" :: "r"(d), "l"(src));
}
__device__ __forceinline__ void cp_commit() {
    asm volatile("cp.async.commit_group;" ::: "memory");
}
__device__ __forceinline__ void mma_tf32(float* c, const uint32_t* a, const uint32_t* b) {
    asm volatile("mma.sync.aligned.m16n8k8.row.col.f32.tf32.tf32.f32 "
        "{%0,%1,%2,%3}, {%4,%5,%6,%7}, {%8,%9}, {%0,%1,%2,%3};"
        : "+f"(c[0]), "+f"(c[1]), "+f"(c[2]), "+f"(c[3])
        : "r"(a[0]), "r"(a[1]), "r"(a[2]), "r"(a[3]), "r"(b[0]), "r"(b[1]));
}
__device__ __forceinline__ float to_tf32(float x) {
    float y; asm("cvt.rna.tf32.f32 %0, %1;" : "=f"(y) : "f"(x)); return y;
}

// ---------------------------------------------------------------------------
// Plain tf32 GEMM: D[z][m][n] = sum_k A[m][k]*B(k,n)  (+epilogue)
//   A: [m][k] global. B: BKM ? [k][n] : [n][k].
//   B addr: Bp + (z/bZ1)*bBa + (z%bZ1)*bBb.
//   mode: 0 = +bias[m]; 2 = out = 2*x + s*d; 3 = out += s*d
// ---------------------------------------------------------------------------
template<int NT, int BKM>
__global__ __launch_bounds__(256, 2)
void mma_gemm(const float* __restrict__ A, size_t aR, size_t aB, int aZ,
              const float* __restrict__ Bp, size_t bR, int bZ1, size_t bBa, size_t bBb,
              float* __restrict__ D, size_t dR, size_t dB,
              int K, int Mvalid, int mode,
              const float* __restrict__ bias, const float* __restrict__ xres,
              const float* __restrict__ scal, int br) {
    constexpr int BS  = NT + 8;
    constexpr int BSZ = NT * 36;
    extern __shared__ float sm[];
    float* Asm[2] = { sm, sm + 128 * 36 };
    float* Bsm[2] = { sm + 2 * 128 * 36, sm + 2 * 128 * 36 + BSZ };

    int tid = threadIdx.x, lane = tid & 31, wid = tid >> 5;
    int z = blockIdx.z;
    int m0b = blockIdx.y * 128, n0b = blockIdx.x * NT;

    const float* Ag = A + (size_t)(z / aZ) * aB + (size_t)m0b * aR;
    const float* Bg = Bp + (size_t)(z / bZ1) * bBa + (size_t)(z % bZ1) * bBb
                    + (BKM ? (size_t)n0b : (size_t)n0b * bR);

    auto fill = [&](int buf, int k0) {
#pragma unroll
        for (int it = 0; it < 4; ++it) {
            int i = tid + it * 256;
            int r = i >> 3, c = (i & 7) << 2;
            cp16(&Asm[buf][r * 36 + c], Ag + (size_t)r * aR + k0 + c);
        }
#pragma unroll
        for (int it = 0; it < NT / 32; ++it) {
            int i = tid + it * 256;
            if (BKM) {
                int k = i / (NT / 4), q = i % (NT / 4);
                cp16(&Bsm[buf][k * BS + q * 4], Bg + (size_t)(k0 + k) * bR + q * 4);
            } else {
                int r = i >> 3, c = (i & 7) << 2;
                cp16(&Bsm[buf][r * 36 + c], Bg + (size_t)r * bR + k0 + c);
            }
        }
        cp_commit();
    };

    constexpr int WNW = NT / 32;
    constexpr int MI  = NT / 32;
    int wn = wid % WNW, wm = wid / WNW;
    int wm0 = wm * (MI * 16), wn0 = wn * 32;

    float acc[MI][4][4];
#pragma unroll
    for (int a = 0; a < MI; ++a)
#pragma unroll
        for (int b = 0; b < 4; ++b)
#pragma unroll
            for (int c = 0; c < 4; ++c) acc[a][b][c] = 0.f;

    int nkt = K >> 5;
    fill(0, 0);
    for (int kt = 0; kt < nkt; ++kt) {
        int buf = kt & 1;
        if (kt + 1 < nkt) {
            fill(buf ^ 1, (kt + 1) << 5);
            asm volatile("cp.async.wait_group 1;" ::: "memory");
        } else {
            asm volatile("cp.async.wait_group 0;" ::: "memory");
        }
        __syncthreads();
        const float* At = Asm[buf];
        const float* Bt = Bsm[buf];
#pragma unroll
        for (int ks = 0; ks < 4; ++ks) {
            uint32_t af[MI][4], bf[4][2];
            int kk = ks * 8 + (lane & 3);
#pragma unroll
            for (int mi = 0; mi < MI; ++mi) {
                int m = wm0 + mi * 16 + (lane >> 2);
                af[mi][0] = __float_as_uint(At[m * 36 + kk]);
                af[mi][1] = __float_as_uint(At[(m + 8) * 36 + kk]);
                af[mi][2] = __float_as_uint(At[m * 36 + kk + 4]);
                af[mi][3] = __float_as_uint(At[(m + 8) * 36 + kk + 4]);
            }
#pragma unroll
            for (int ni = 0; ni < 4; ++ni) {
                int n = wn0 + ni * 8 + (lane >> 2);
                if (BKM) {
                    bf[ni][0] = __float_as_uint(Bt[kk * BS + n]);
                    bf[ni][1] = __float_as_uint(Bt[(kk + 4) * BS + n]);
                } else {
                    bf[ni][0] = __float_as_uint(Bt[n * 36 + kk]);
                    bf[ni][1] = __float_as_uint(Bt[n * 36 + kk + 4]);
                }
            }
#pragma unroll
            for (int mi = 0; mi < MI; ++mi)
#pragma unroll
                for (int ni = 0; ni < 4; ++ni)
                    mma_tf32(acc[mi][ni], af[mi], bf[ni]);
        }
        __syncthreads();
    }

    float s = (mode >= 2) ? scal[br] : 0.f;
#pragma unroll
    for (int mi = 0; mi < MI; ++mi)
#pragma unroll
        for (int ni = 0; ni < 4; ++ni)
#pragma unroll
            for (int h = 0; h < 2; ++h) {
                int row = m0b + wm0 + mi * 16 + (lane >> 2) + h * 8;
                int col = n0b + wn0 + ni * 8 + (lane & 3) * 2;
                if (row < Mvalid) {
                    size_t off = (size_t)z * dB + (size_t)row * dR + col;
                    float d0 = acc[mi][ni][h * 2], d1 = acc[mi][ni][h * 2 + 1];
                    float2 v;
                    if (mode == 0) {
                        float bi = bias[row];
                        v = make_float2(d0 + bi, d1 + bi);
                    } else if (mode == 2) {
                        float2 x2 = *(const float2*)(xres + off);
                        v = make_float2(2.f * x2.x + s * d0, 2.f * x2.y + s * d1);
                    } else {
                        float2 o = *(const float2*)(D + off);
                        v = make_float2(o.x + s * d0, o.y + s * d1);
                    }
                    *(float2*)(D + off) = v;
                }
            }
}

// ---------------------------------------------------------------------------
// 3xTF32 GEMM (Q,K projection + logits). hi/lo split, ~21-bit mantissa.
// AKM: A global [k][m]; else [m][k] (chunked via aCb/aCbs).
// BKM: B global [k][n]; else [n][k] (chunked via bCb/bCbs).
// Split-K: z = b*CH + ch. mode: 0 = +bias[m] -> D[b]; 1 = raw partial -> D[z].
// ---------------------------------------------------------------------------
template<int NT, int AKM, int BKM>
__global__ __launch_bounds__(256, 2)
void mma3x_gemm(const float* __restrict__ A, size_t aR, size_t aB, int aCb, size_t aCbs,
                const float* __restrict__ Bp, size_t bR, size_t bB, int bCb, size_t bCbs,
                float* __restrict__ D, size_t dR, size_t dB,
                int Kc, int CH, int Mvalid, int mode, const float* __restrict__ bias) {
    constexpr int BS  = NT + 8;
    constexpr int BSZ = NT * 36;
    extern __shared__ float sm[];
    float* Ah = sm;
    float* Al = sm + 128 * 36;
    float* Bh = sm + 2 * 128 * 36;
    float* Bl = sm + 2 * 128 * 36 + BSZ;

    int tid = threadIdx.x, lane = tid & 31, wid = tid >> 5;
    int z = blockIdx.z;
    int b = z / CH, ch = z % CH;
    int m0b = blockIdx.y * 128, n0b = blockIdx.x * NT;
    int kbeg = ch * Kc;

    const float* Ag = A + (size_t)b * aB + (AKM ? (size_t)m0b : (size_t)m0b * aR);
    const float* Bg = Bp + (size_t)b * bB + (BKM ? (size_t)n0b : (size_t)n0b * bR);

    constexpr int WNW = NT / 32;
    constexpr int MI  = NT / 32;
    int wn = wid % WNW, wm = wid / WNW;
    int wm0 = wm * (MI * 16), wn0 = wn * 32;

    float acc[MI][4][4];
#pragma unroll
    for (int a = 0; a < MI; ++a)
#pragma unroll
        for (int bb = 0; bb < 4; ++bb)
#pragma unroll
            for (int c = 0; c < 4; ++c) acc[a][bb][c] = 0.f;

    int nkt = Kc >> 5;
    for (int kt = 0; kt < nkt; ++kt) {
        int kb = kbeg + (kt << 5);
        __syncthreads();
#pragma unroll
        for (int it = 0; it < 4; ++it) {       // A tile
            int i = tid + it * 256;
            float4 v;
            int sa;
            if (AKM) {
                int k = i >> 5, q = i & 31;
                int m4 = q * 4;
                if (m4 > Mvalid - 4) m4 = Mvalid - 4;
                v = *(const float4*)(Ag + (size_t)(kb + k) * aR + m4);
                sa = k * 136 + q * 4;
            } else {
                int r = i >> 3, c = (i & 7) << 2;
                int rr = (r < Mvalid) ? r : (Mvalid - 1);
                size_t ko = aCb ? ((size_t)(kb / aCb) * aCbs + (size_t)(kb % aCb))
                                : (size_t)kb;
                v = *(const float4*)(Ag + (size_t)rr * aR + ko + c);
                sa = r * 36 + c;
            }
            float4 hi = make_float4(to_tf32(v.x), to_tf32(v.y), to_tf32(v.z), to_tf32(v.w));
            float4 lo = make_float4(to_tf32(v.x - hi.x), to_tf32(v.y - hi.y),
                                    to_tf32(v.z - hi.z), to_tf32(v.w - hi.w));
            *(float4*)&Ah[sa] = hi;
            *(float4*)&Al[sa] = lo;
        }
#pragma unroll
        for (int it = 0; it < NT / 32; ++it) { // B tile
            int i = tid + it * 256;
            float4 v;
            int sa;
            if (BKM) {
                int k = i / (NT / 4), q = i % (NT / 4);
                v = *(const float4*)(Bg + (size_t)(kb + k) * bR + q * 4);
                sa = k * BS + q * 4;
            } else {
                int r = i >> 3, c = (i & 7) << 2;
                size_t ko = bCb ? ((size_t)(kb / bCb) * bCbs + (size_t)(kb % bCb))
                                : (size_t)kb;
                v = *(const float4*)(Bg + (size_t)r * bR + ko + c);
                sa = r * 36 + c;
            }
            float4 hi = make_float4(to_tf32(v.x), to_tf32(v.y), to_tf32(v.z), to_tf32(v.w));
            float4 lo = make_float4(to_tf32(v.x - hi.x), to_tf32(v.y - hi.y),
                                    to_tf32(v.z - hi.z), to_tf32(v.w - hi.w));
            *(float4*)&Bh[sa] = hi;
            *(float4*)&Bl[sa] = lo;
        }
        __syncthreads();
#pragma unroll
        for (int ks = 0; ks < 4; ++ks) {
            int kk = ks * 8 + (lane & 3);
            uint32_t ah[MI][4], al[MI][4], bh[4][2], bl[4][2];
#pragma unroll
            for (int mi = 0; mi < MI; ++mi) {
                int m = wm0 + mi * 16 + (lane >> 2);
                if (AKM) {
                    ah[mi][0] = __float_as_uint(Ah[kk * 136 + m]);
                    ah[mi][1] = __float_as_uint(Ah[kk * 136 + m + 8]);
                    ah[mi][2] = __float_as_uint(Ah[(kk + 4) * 136 + m]);
                    ah[mi][3] = __float_as_uint(Ah[(kk + 4) * 136 + m + 8]);
                    al[mi][0] = __float_as_uint(Al[kk * 136 + m]);
                    al[mi][1] = __float_as_uint(Al[kk * 136 + m + 8]);
                    al[mi][2] = __float_as_uint(Al[(kk + 4) * 136 + m]);
                    al[mi][3] = __float_as_uint(Al[(kk + 4) * 136 + m + 8]);
                } else {
                    ah[mi][0] = __float_as_uint(Ah[m * 36 + kk]);
                    ah[mi][1] = __float_as_uint(Ah[(m + 8) * 36 + kk]);
                    ah[mi][2] = __float_as_uint(Ah[m * 36 + kk + 4]);
                    ah[mi][3] = __float_as_uint(Ah[(m + 8) * 36 + kk + 4]);
                    al[mi][0] = __float_as_uint(Al[m * 36 + kk]);
                    al[mi][1] = __float_as_uint(Al[(m + 8) * 36 + kk]);
                    al[mi][2] = __float_as_uint(Al[m * 36 + kk + 4]);
                    al[mi][3] = __float_as_uint(Al[(m + 8) * 36 + kk + 4]);
                }
            }
#pragma unroll
            for (int ni = 0; ni < 4; ++ni) {
                int n = wn0 + ni * 8 + (lane >> 2);
                if (BKM) {
                    bh[ni][0] = __float_as_uint(Bh[kk * BS + n]);
                    bh[ni][1] = __float_as_uint(Bh[(kk + 4) * BS + n]);
                    bl[ni][0] = __float_as_uint(Bl[kk * BS + n]);
                    bl[ni][1] = __float_as_uint(Bl[(kk + 4) * BS + n]);
                } else {
                    bh[ni][0] = __float_as_uint(Bh[n * 36 + kk]);
                    bh[ni][1] = __float_as_uint(Bh[n * 36 + kk + 4]);
                    bl[ni][0] = __float_as_uint(Bl[n * 36 + kk]);
                    bl[ni][1] = __float_as_uint(Bl[n * 36 + kk + 4]);
                }
            }
#pragma unroll
            for (int mi = 0; mi < MI; ++mi)
#pragma unroll
                for (int ni = 0; ni < 4; ++ni) {
                    mma_tf32(acc[mi][ni], ah[mi], bh[ni]);
                    mma_tf32(acc[mi][ni], ah[mi], bl[ni]);
                    mma_tf32(acc[mi][ni], al[mi], bh[ni]);
                }
        }
    }

#pragma unroll
    for (int mi = 0; mi < MI; ++mi)
#pragma unroll
        for (int ni = 0; ni < 4; ++ni)
#pragma unroll
            for (int h = 0; h < 2; ++h) {
                int row = m0b + wm0 + mi * 16 + (lane >> 2) + h * 8;
                int col = n0b + wn0 + ni * 8 + (lane & 3) * 2;
                if (row < Mvalid) {
                    size_t off = (mode == 0 ? (size_t)b : (size_t)z) * dB
                               + (size_t)row * dR + col;
                    float d0 = acc[mi][ni][h * 2], d1 = acc[mi][ni][h * 2 + 1];
                    float2 v;
                    if (mode == 0) {
                        float bi = bias[row];
                        v = make_float2(d0 + bi, d1 + bi);
                    } else {
                        v = make_float2(d0, d1);
                    }
                    *(float2*)(D + off) = v;
                }
            }
}

// ---------------------------------------------------------------------------
// Fused split-K reduce + row softmax: att[b,h,:] = softmax(sum_ch part).
// ---------------------------------------------------------------------------
__global__ void reduce_softmax_kernel(const float* __restrict__ part,
                                      float* __restrict__ att, int S, int CH) {
    __shared__ float red[128];
    int SS = S * S;
    int b = blockIdx.x / S, h = blockIdx.x % S;
    int t = threadIdx.x;
    const float* base = part + (size_t)b * CH * SS + (size_t)h * S + t;
    float v = 0.f;
    for (int ch = 0; ch < CH; ++ch) v += base[(size_t)ch * SS];
    red[t] = v;
    __syncthreads();
    for (int off = S >> 1; off > 0; off >>= 1) {
        if (t < off) red[t] = fmaxf(red[t], red[t + off]);
        __syncthreads();
    }
    float m = red[0];
    __syncthreads();
    float e = expf(v - m);
    red[t] = e;
    __syncthreads();
    for (int off = S >> 1; off > 0; off >>= 1) {
        if (t < off) red[t] += red[t + off];
        __syncthreads();
    }
    att[(size_t)b * SS + (size_t)h * S + t] = e / red[0];
}

// ---------------------------------------------------------------------------
// Host orchestration (one map, one stream)
// ---------------------------------------------------------------------------
static void process_map(const float* x, int S, float* out, int brw, int brh,
                        const float* qw, const float* qb, const float* kw, const float* kb,
                        const float* vw, const float* vb, const float* sc,
                        float* v, float* qk, float* att, float* part,
                        float* wqk, float* bqk, float* wv, float* bv,
                        cudaStream_t st) {
    const size_t SS = (size_t)S * S;
    const size_t F  = 32 * (size_t)S;
    const bool big  = (S == 128);
    const int CH = big ? 32 : 16;
    const int Kc = (int)F / CH;               // 128 both

    // Stack Q/K weights+bias of BOTH branches: [Qw;Kw;Qh;Kh] = 128 x 256
    cudaMemcpyAsync(wqk,         qw + (size_t)brw * 32 * C_, 32 * C_ * 4, cudaMemcpyDeviceToDevice, st);
    cudaMemcpyAsync(wqk + 32*C_, kw + (size_t)brw * 32 * C_, 32 * C_ * 4, cudaMemcpyDeviceToDevice, st);
    cudaMemcpyAsync(wqk + 64*C_, qw + (size_t)brh * 32 * C_, 32 * C_ * 4, cudaMemcpyDeviceToDevice, st);
    cudaMemcpyAsync(wqk + 96*C_, kw + (size_t)brh * 32 * C_, 32 * C_ * 4, cudaMemcpyDeviceToDevice, st);
    cudaMemcpyAsync(bqk,      qb + (size_t)brw * 32, 32 * 4, cudaMemcpyDeviceToDevice, st);
    cudaMemcpyAsync(bqk + 32, kb + (size_t)brw * 32, 32 * 4, cudaMemcpyDeviceToDevice, st);
    cudaMemcpyAsync(bqk + 64, qb + (size_t)brh * 32, 32 * 4, cudaMemcpyDeviceToDevice, st);
    cudaMemcpyAsync(bqk + 96, kb + (size_t)brh * 32, 32 * 4, cudaMemcpyDeviceToDevice, st);
    // Stack V weights+bias of both branches: 512 x 256
    cudaMemcpyAsync(wv,           vw + (size_t)brw * C_ * C_, C_ * C_ * 4, cudaMemcpyDeviceToDevice, st);
    cudaMemcpyAsync(wv + 256*C_,  vw + (size_t)brh * C_ * C_, C_ * C_ * 4, cudaMemcpyDeviceToDevice, st);
    cudaMemcpyAsync(bv,       vb + (size_t)brw * C_, C_ * 4, cudaMemcpyDeviceToDevice, st);
    cudaMemcpyAsync(bv + C_,  vb + (size_t)brh * C_, C_ * 4, cudaMemcpyDeviceToDevice, st);

    // QK projection (both branches, 3xTF32), B = X directly (k-major [C][SS])
    mma3x_gemm<128, 0, 1><<<dim3(SS / 128, 1, B_), 256, 73728, st>>>(
        wqk, C_, 0, 0, 0,
        x, SS, C_ * SS, 0, 0,
        qk, SS, (size_t)128 * SS,
        C_, 1, 128, 0, bqk);

    // V projection, both branches fused: rows 0..255 = V_w, 256..511 = V_h
    mma_gemm<128, 1><<<dim3(SS / 128, 4, B_), 256, 73728, st>>>(
        wv, C_, 0, 1,
        x, SS, 1, C_ * SS, 0,
        v, SS, (size_t)512 * SS,
        C_, 512, 0, bv, nullptr, sc, 0);

    // ---- pass 0: over-W ----
    if (big)
        mma3x_gemm<128, 1, 1><<<dim3(1, 1, B_ * CH), 256, 73728, st>>>(
            qk, S, (size_t)128 * SS, 0, 0,
            qk + 32 * SS, S, (size_t)128 * SS, 0, 0,
            part, S, SS, Kc, CH, S, 1, nullptr);
    else
        mma3x_gemm<64, 1, 1><<<dim3(1, 1, B_ * CH), 256, 55296, st>>>(
            qk, S, (size_t)128 * SS, 0, 0,
            qk + 32 * SS, S, (size_t)128 * SS, 0, 0,
            part, S, SS, Kc, CH, S, 1, nullptr);
    reduce_softmax_kernel<<<B_ * S, S, 0, st>>>(part, att, S, CH);
    // apply-W: out = 2x + s * V_w @ att^T (V as [(C*S)][S])
    if (big)
        mma_gemm<128, 0><<<dim3(1, C_ * S / 128, B_), 256, 73728, st>>>(
            v, S, (size_t)512 * SS, 1,
            att, S, 1, SS, 0,
            out, S, (size_t)C_ * SS,
            S, C_ * S, 2, nullptr, x, sc, brw);
    else
        mma_gemm<64, 0><<<dim3(1, C_ * S / 128, B_), 256, 55296, st>>>(
            v, S, (size_t)512 * SS, 1,
            att, S, 1, SS, 0,
            out, S, (size_t)C_ * SS,
            S, C_ * S, 2, nullptr, x, sc, brw);

    // ---- pass 1: over-H ----
    if (big)
        mma3x_gemm<128, 0, 0><<<dim3(1, 1, B_ * CH), 256, 73728, st>>>(
            qk + 64 * SS, S, (size_t)128 * SS, S, SS,
            qk + 96 * SS, S, (size_t)128 * SS, S, SS,
            part, S, SS, Kc, CH, S, 1, nullptr);
    else
        mma3x_gemm<64, 0, 0><<<dim3(1, 1, B_ * CH), 256, 55296, st>>>(
            qk + 64 * SS, S, (size_t)128 * SS, S, SS,
            qk + 96 * SS, S, (size_t)128 * SS, S, SS,
            part, S, SS, Kc, CH, S, 1, nullptr);
    reduce_softmax_kernel<<<B_ * S, S, 0, st>>>(part, att, S, CH);
    // apply-H: out += s * att @ V_h, B = V_h[c] directly (k-major [v][w])
    if (big)
        mma_gemm<128, 1><<<dim3(1, 1, B_ * C_), 256, 73728, st>>>(
            att, S, SS, C_,
            v + 256 * SS, S, C_, (size_t)512 * SS, SS,
            out, S, SS,
            S, S, 3, nullptr, nullptr, sc, brh);
    else
        mma_gemm<64, 1><<<dim3(1, 1, B_ * C_), 256, 55296, st>>>(
            att, S, SS, C_,
            v + 256 * SS, S, C_, (size_t)512 * SS, SS,
            out, S, SS,
            S, S, 3, nullptr, nullptr, sc, brh);
}

extern "C" void kernel_launch(void* const* d_in, const int* in_sizes, int n_in,
                              void* d_out, int out_size) {
    const float* tmap = (const float*)d_in[0];
    const float* smap = (const float*)d_in[1];
    const float* qw   = (const float*)d_in[2];
    const float* qb   = (const float*)d_in[3];
    const float* kw   = (const float*)d_in[4];
    const float* kb   = (const float*)d_in[5];
    const float* vw   = (const float*)d_in[6];
    const float* vb   = (const float*)d_in[7];
    const float* sc   = (const float*)d_in[8];

    // One-time resources (created on the non-captured correctness call;
    // stream/event creation is not legal inside graph capture).
    static cudaStream_t s1 = nullptr;
    static cudaEvent_t evF = nullptr, evJ = nullptr;
    if (s1 == nullptr) {
        cudaStreamCreateWithFlags(&s1, cudaStreamNonBlocking);
        cudaEventCreateWithFlags(&evF, cudaEventDisableTiming);
        cudaEventCreateWithFlags(&evJ, cudaEventDisableTiming);
    }

    cudaFuncSetAttribute(mma_gemm<128, 0>,      cudaFuncAttributeMaxDynamicSharedMemorySize, 73728);
    cudaFuncSetAttribute(mma_gemm<128, 1>,      cudaFuncAttributeMaxDynamicSharedMemorySize, 73728);
    cudaFuncSetAttribute(mma_gemm<64, 0>,       cudaFuncAttributeMaxDynamicSharedMemorySize, 55296);
    cudaFuncSetAttribute(mma_gemm<64, 1>,       cudaFuncAttributeMaxDynamicSharedMemorySize, 55296);
    cudaFuncSetAttribute(mma3x_gemm<128, 0, 1>, cudaFuncAttributeMaxDynamicSharedMemorySize, 73728);
    cudaFuncSetAttribute(mma3x_gemm<128, 1, 1>, cudaFuncAttributeMaxDynamicSharedMemorySize, 73728);
    cudaFuncSetAttribute(mma3x_gemm<128, 0, 0>, cudaFuncAttributeMaxDynamicSharedMemorySize, 73728);
    cudaFuncSetAttribute(mma3x_gemm<64, 1, 1>,  cudaFuncAttributeMaxDynamicSharedMemorySize, 55296);
    cudaFuncSetAttribute(mma3x_gemm<64, 0, 0>,  cudaFuncAttributeMaxDynamicSharedMemorySize, 55296);

    void *p_v, *p_qk, *p_att, *p_part, *p_wqk, *p_bqk, *p_wv, *p_bv;
    cudaGetSymbolAddress(&p_v,    g_v);
    cudaGetSymbolAddress(&p_qk,   g_qk);
    cudaGetSymbolAddress(&p_att,  g_att);
    cudaGetSymbolAddress(&p_part, g_part);
    cudaGetSymbolAddress(&p_wqk,  g_wqk);
    cudaGetSymbolAddress(&p_bqk,  g_bqk);
    cudaGetSymbolAddress(&p_wv,   g_wv);
    cudaGetSymbolAddress(&p_bv,   g_bv);

    float* v0   = (float*)p_v;
    float* qk0  = (float*)p_qk;
    float* att0 = (float*)p_att;
    float* pt0  = (float*)p_part;
    float* wqk0 = (float*)p_wqk;
    float* bqk0 = (float*)p_bqk;
    float* wv0  = (float*)p_wv;
    float* bv0  = (float*)p_bv;

    // Region split: template first, scene second (template tail overreads of
    // att/qk land in the scene region, which is allocated).
    float* v_s   = v0   + (size_t)B_ * 512 * SS_T;
    float* qk_s  = qk0  + (size_t)B_ * 128 * SS_T;
    float* att_s = att0 + (size_t)B_ * SS_T;
    float* pt_s  = pt0  + (size_t)B_ * 16 * SS_T;

    float* tout = (float*)d_out;
    float* sout = tout + (size_t)B_ * C_ * 64 * 64;

    // Fork template chain onto s1; scene chain stays on the capture stream.
    cudaEventRecord(evF, 0);
    cudaStreamWaitEvent(s1, evF, 0);

    process_map(tmap, 64, tout, 0, 2, qw, qb, kw, kb, vw, vb, sc,
                v0, qk0, att0, pt0,
                wqk0, bqk0, wv0, bv0, s1);

    process_map(smap, 128, sout, 1, 3, qw, qb, kw, kb, vw, vb, sc,
                v_s, qk_s, att_s, pt_s,
                wqk0 + 128 * C_, bqk0 + 128, wv0 + 512 * C_, bv0 + 512, (cudaStream_t)0);

    // Join: capture stream waits for the template chain.
    cudaEventRecord(evJ, s1);
    cudaStreamWaitEvent((cudaStream_t)0, evJ, 0);
}